// round 8
// baseline (speedup 1.0000x reference)
#include <cuda_runtime.h>
#include <cuda_bf16.h>
#include <math.h>
#include <stdint.h>

// ---------------- problem constants ----------------
#define BATCH   2
#define SEQ     8192
#define NTOK    (BATCH*SEQ)        // 16384
#define DMODEL  2048
#define NQKV    6144
#define NHEAD   16
#define DHEAD   128
#define NCHUNK  64
#define CHUNKL  128
#define QK_SCALE 0.08838834764831845f

#define TP 132
#define APITCH 129

// tcgen05 is only legal on arch-specific / family-specific targets.
#if defined(__CUDA_ARCH__) && (defined(__CUDA_ARCH_FEAT_SM103_ALL) || defined(__CUDA_ARCH_FEAT_SM100_ALL) || defined(__CUDA_ARCH_FEAT_SM101_ALL) || defined(__CUDA_ARCH_FAMILY_SPECIFIC__) || defined(__CUDA_ARCH_SPECIFIC__))
#define HAS_TC 1
#else
#define HAS_TC 0
#endif

// ---------------- device scratch ----------------
__device__ float g_qkv[(size_t)NTOK * NQKV];
__device__ __nv_bfloat16 g_qkv_h[(size_t)NTOK * NQKV];
__device__ __nv_bfloat16 g_qkv_l[(size_t)NTOK * NQKV];
__device__ float g_qe [(size_t)NTOK * DMODEL];
__device__ float g_ke [(size_t)NTOK * DMODEL];
__device__ float g_st [(size_t)BATCH * NHEAD * NCHUNK * 128 * 128];
__device__ float g_y  [(size_t)NTOK * DMODEL];
__device__ __nv_bfloat16 g_y_h[(size_t)NTOK * DMODEL];
__device__ __nv_bfloat16 g_y_l[(size_t)NTOK * DMODEL];
__device__ __nv_bfloat16 g_x_h[(size_t)NTOK * DMODEL];
__device__ __nv_bfloat16 g_x_l[(size_t)NTOK * DMODEL];
__device__ __nv_bfloat16 g_win_h[(size_t)NQKV * DMODEL];
__device__ __nv_bfloat16 g_win_l[(size_t)NQKV * DMODEL];
__device__ __nv_bfloat16 g_wemb_h[(size_t)DMODEL * DMODEL];
__device__ __nv_bfloat16 g_wemb_l[(size_t)DMODEL * DMODEL];
__device__ __nv_bfloat16 g_wout_h[(size_t)DMODEL * DMODEL];
__device__ __nv_bfloat16 g_wout_l[(size_t)DMODEL * DMODEL];

__device__ __forceinline__ float head_slope(int h) {
    return -logf(1.0f - exp2f(-5.0f - (float)h));
}

__device__ __forceinline__ void split2(float v, __nv_bfloat16& h, __nv_bfloat16& l) {
    h = __float2bfloat16_rn(v);
    l = __float2bfloat16_rn(v - __bfloat162float(h));
}

// ================= PTX helpers =================
__device__ __forceinline__ uint32_t smem_to_u32(const void* p) {
    uint32_t a;
    asm("{ .reg .u64 t; cvta.to.shared.u64 t, %1; cvt.u32.u64 %0, t; }" : "=r"(a) : "l"(p));
    return a;
}
#define MBARRIER_INIT(mbar, count) \
    asm volatile("mbarrier.init.shared.b64 [%0], %1;" \
        :: "r"((uint32_t)(mbar)), "r"((uint32_t)(count)) : "memory")
#define MBARRIER_INVAL(mbar) \
    asm volatile("mbarrier.inval.shared.b64 [%0];" \
        :: "r"((uint32_t)(mbar)) : "memory")
#define MBARRIER_WAIT_PARITY(mbar_smem_addr, phase_parity) do { \
    uint32_t _mbar = (uint32_t)(mbar_smem_addr); \
    uint32_t _parity = (uint32_t)(phase_parity); \
    uint32_t _done; \
    asm volatile( \
        "{\n\t.reg .pred p;\n\t" \
        "mbarrier.try_wait.parity.acquire.cta.shared::cta.b64 p, [%1], %2;\n\t" \
        "selp.b32 %0, 1, 0, p;\n\t}" \
        : "=r"(_done) : "r"(_mbar), "r"(_parity) : "memory"); \
    if (!_done) { \
        asm volatile( \
            "{\n\t.reg .pred P1;\n\t" \
            "WAIT_LOOP_%=:\n\t" \
            "mbarrier.try_wait.parity.acquire.cta.shared::cta.b64 P1, [%0], %1, 0x989680;\n\t" \
            "@P1 bra.uni WAIT_DONE_%=;\n\t" \
            "bra.uni WAIT_LOOP_%=;\n\t" \
            "WAIT_DONE_%=:\n\t}" \
            :: "r"(_mbar), "r"(_parity) : "memory"); \
    } \
} while(0)
#define FENCE_PROXY_ASYNC_SHARED_CTA() \
    asm volatile("fence.proxy.async.shared::cta;" ::: "memory")

#if HAS_TC
__device__ __forceinline__ uint32_t elect_one_pred() {
    uint32_t pred;
    asm volatile(
        "{\n\t.reg .pred p;\n\t"
        "elect.sync _|p, 0xFFFFFFFF;\n\t"
        "selp.b32 %0, 1, 0, p;\n\t}"
        : "=r"(pred));
    return pred;
}
#define TCGEN05_ALLOC(smem_result_addr, nCols) \
    asm volatile("tcgen05.alloc.cta_group::1.sync.aligned.shared::cta.b32 [%0], %1;" \
        :: "r"((uint32_t)(smem_result_addr)), "r"((uint32_t)(nCols)) : "memory")
#define TCGEN05_DEALLOC(tmem_addr, nCols) \
    asm volatile("tcgen05.dealloc.cta_group::1.sync.aligned.b32 %0, %1;" \
        :: "r"(tmem_addr), "r"((uint32_t)(nCols)))
#define TCGEN05_COMMIT(mbar) \
    asm volatile("tcgen05.commit.cta_group::1.mbarrier::arrive::one.shared::cluster.b64 [%0];" \
        :: "r"((uint32_t)(mbar)) : "memory")
#define TCGEN05_FENCE_AFTER() \
    asm volatile("tcgen05.fence::after_thread_sync;" ::: "memory")
#define TCGEN05_FENCE_BEFORE() \
    asm volatile("tcgen05.fence::before_thread_sync;" ::: "memory")
#define TCGEN05_WAIT_LD() \
    asm volatile("tcgen05.wait::ld.sync.aligned;" ::: "memory")
#define TCGEN05_LD_32X32B_X32(r, tmem_addr) \
    asm volatile( \
        "tcgen05.ld.sync.aligned.32x32b.x32.b32 " \
        "{%0, %1, %2, %3, %4, %5, %6, %7, " \
        " %8, %9, %10, %11, %12, %13, %14, %15, " \
        " %16, %17, %18, %19, %20, %21, %22, %23, " \
        " %24, %25, %26, %27, %28, %29, %30, %31}, [%32];" \
        : "=r"((r)[0]),  "=r"((r)[1]),  "=r"((r)[2]),  "=r"((r)[3]), \
          "=r"((r)[4]),  "=r"((r)[5]),  "=r"((r)[6]),  "=r"((r)[7]), \
          "=r"((r)[8]),  "=r"((r)[9]),  "=r"((r)[10]), "=r"((r)[11]), \
          "=r"((r)[12]), "=r"((r)[13]), "=r"((r)[14]), "=r"((r)[15]), \
          "=r"((r)[16]), "=r"((r)[17]), "=r"((r)[18]), "=r"((r)[19]), \
          "=r"((r)[20]), "=r"((r)[21]), "=r"((r)[22]), "=r"((r)[23]), \
          "=r"((r)[24]), "=r"((r)[25]), "=r"((r)[26]), "=r"((r)[27]), \
          "=r"((r)[28]), "=r"((r)[29]), "=r"((r)[30]), "=r"((r)[31]) \
        : "r"(tmem_addr))

static constexpr uint64_t SMEM_DESC_BASE_SW128 =
    (uint64_t(2)  << 61) | (uint64_t(1) << 46) | (uint64_t(64) << 32) | (uint64_t(1) << 16);
#define MAKE_SMEM_DESC(base_addr) \
    (SMEM_DESC_BASE_SW128 | ((uint64_t)((base_addr) >> 4) & 0x3FFF))

// idesc: dtype=F32, atype=BF16, btype=BF16, K-major/K-major, M=128, N=64
// (pattern validated: test_mma.cu N=32 -> 0x8080490; here N=64 -> 0x8100490)
#define IDESC_M128N64 ((1u<<4)|(1u<<7)|(1u<<10)|((64u/8u)<<17)|((128u/16u)<<24))

__device__ __forceinline__ void mma_f16_ss(uint32_t d_tmem, uint64_t a_desc,
                                           uint64_t b_desc, uint32_t idesc, bool acc) {
    uint32_t en = acc ? 1u : 0u;
    asm volatile(
        "{\n\t.reg .pred p;\n\t"
        "setp.ne.u32 p, %5, 0;\n\t"
        "tcgen05.mma.cta_group::1.kind::f16 [%0], %1, %2, %3, {%4, %4, %4, %4}, p;\n\t}"
        :: "r"(d_tmem), "l"(a_desc), "l"(b_desc), "r"(idesc), "r"(0u), "r"(en)
        : "memory");
}
#endif // HAS_TC

#define SWZ128(off) ((off) ^ (((off) >> 3) & 0x70))

// ================= fp32 -> (hi,lo) bf16 split =================
__global__ __launch_bounds__(256)
void split_kernel(const float* __restrict__ in, __nv_bfloat16* __restrict__ hi,
                  __nv_bfloat16* __restrict__ lo, long long n4)
{
    long long i = (long long)blockIdx.x * 256 + threadIdx.x;
    if (i >= n4) return;
    float4 v = ((const float4*)in)[i];
    __nv_bfloat16 h0,h1,h2,h3,l0,l1,l2,l3;
    split2(v.x,h0,l0); split2(v.y,h1,l1); split2(v.z,h2,l2); split2(v.w,h3,l3);
    __nv_bfloat162* hp = (__nv_bfloat162*)(hi + 4*i);
    __nv_bfloat162* lp = (__nv_bfloat162*)(lo + 4*i);
    hp[0] = __nv_bfloat162(h0,h1); hp[1] = __nv_bfloat162(h2,h3);
    lp[0] = __nv_bfloat162(l0,l1); lp[1] = __nv_bfloat162(l2,l3);
}

// ================= GEMM: tcgen05 bf16x3 (or FMA fallback) =================
// C[m,n] = scale*(sum_k A[m,k]*B[n,k] + bias[n]); tile 128(M) x 256(N).
// Single 96KB stage; overlap comes from 2 CTAs/SM.
#define KT 64
#define STAGE_BYTES 98304
#define SMEM_TILE0 1024
#define GEMM_SMEM (SMEM_TILE0 + STAGE_BYTES)   // 99328

__global__ __launch_bounds__(128) __cluster_dims__(1, 1, 1)
void gemm_tc_kernel(const __nv_bfloat16* __restrict__ Ah, const __nv_bfloat16* __restrict__ Al, int lda,
                    const __nv_bfloat16* __restrict__ Bh, const __nv_bfloat16* __restrict__ Bl, int ldb,
                    float* __restrict__ C, __nv_bfloat16* __restrict__ Ch, __nv_bfloat16* __restrict__ Cl,
                    int ldc, int K, const float* __restrict__ bias, float scale)
{
    extern __shared__ __align__(1024) char smem[];
    const int tid = threadIdx.x;
    const int n0 = blockIdx.x * 256;
    const int m0 = blockIdx.y * 128;

#if HAS_TC
    const uint32_t sb = smem_to_u32(smem);
    const int wid = tid >> 5, lid = tid & 31;

    // warp 0 allocates TMEM; nobody relinquishes (avoids relinquish-before-alloc race)
    if (wid == 0) { TCGEN05_ALLOC(sb + 0, 256); }
    if (tid == 0) { MBARRIER_INIT(sb + 8, 1); }
    __syncthreads();
    uint32_t tmem;
    asm volatile("ld.shared.b32 %0, [%1];" : "=r"(tmem) : "r"(sb));

    char* st = smem + SMEM_TILE0;
    const uint32_t sbase = sb + SMEM_TILE0;
    const int ktiles = K / KT;

    for (int t = 0; t < ktiles; t++) {
        const int k0 = t * KT;
        // A hi/lo: 128 rows x 128B (SW128)
#pragma unroll
        for (int it = 0; it < 8; it++) {
            int i = tid + it * 128;
            int row = i >> 3, c = i & 7;
            uint32_t sw = SWZ128((uint32_t)(row * 128 + c * 16));
            *(uint4*)(st + sw)         = *(const uint4*)(Ah + (size_t)(m0 + row) * lda + k0 + c * 8);
            *(uint4*)(st + 16384 + sw) = *(const uint4*)(Al + (size_t)(m0 + row) * lda + k0 + c * 8);
        }
        // B hi/lo: 256 rows x 128B (SW128)
#pragma unroll
        for (int it = 0; it < 16; it++) {
            int i = tid + it * 128;
            int row = i >> 3, c = i & 7;
            uint32_t sw = SWZ128((uint32_t)(row * 128 + c * 16));
            *(uint4*)(st + 32768 + sw) = *(const uint4*)(Bh + (size_t)(n0 + row) * ldb + k0 + c * 8);
            *(uint4*)(st + 65536 + sw) = *(const uint4*)(Bl + (size_t)(n0 + row) * ldb + k0 + c * 8);
        }
        FENCE_PROXY_ASYNC_SHARED_CTA();
        __syncthreads();

        if (wid == 0 && elect_one_pred()) {
            uint64_t dAh = MAKE_SMEM_DESC(sbase);
            uint64_t dAl = MAKE_SMEM_DESC(sbase + 16384);
            uint64_t dBh = MAKE_SMEM_DESC(sbase + 32768);
            uint64_t dBl = MAKE_SMEM_DESC(sbase + 65536);
#pragma unroll
            for (int ks = 0; ks < 4; ks++) {
                uint64_t oa = ks * 2;           // +32B per K-step (16B units)
#pragma unroll
                for (int nq = 0; nq < 4; nq++) {
                    uint32_t d = tmem + nq * 64;            // 64 fp32 columns per N-quarter
                    uint64_t ob = ks * 2 + nq * 512;        // +64 rows*128B = 8192B = 512 units
                    bool first = (t == 0 && ks == 0);
                    mma_f16_ss(d, dAh + oa, dBh + ob, IDESC_M128N64, !first);
                    mma_f16_ss(d, dAh + oa, dBl + ob, IDESC_M128N64, true);
                    mma_f16_ss(d, dAl + oa, dBh + ob, IDESC_M128N64, true);
                }
            }
            TCGEN05_COMMIT(sb + 8);
        }
        // all threads wait for this tile's MMAs before the buffer is reused
        MBARRIER_WAIT_PARITY(sb + 8, t & 1);
    }
    TCGEN05_FENCE_AFTER();

    // epilogue: warp w owns rows m0 + 32w .. +31
    const int row = m0 + wid * 32 + lid;
#pragma unroll
    for (int cb = 0; cb < 256; cb += 32) {
        uint32_t regs[32];
        TCGEN05_LD_32X32B_X32(regs, tmem + cb);
        TCGEN05_WAIT_LD();
        float v[32];
#pragma unroll
        for (int c = 0; c < 32; c++) {
            float bv = bias ? bias[n0 + cb + c] : 0.0f;
            v[c] = scale * (__uint_as_float(regs[c]) + bv);
        }
        float* crow = C + (size_t)row * ldc + n0 + cb;
#pragma unroll
        for (int c4 = 0; c4 < 8; c4++) {
            *(float4*)(crow + c4 * 4) = make_float4(v[c4*4], v[c4*4+1], v[c4*4+2], v[c4*4+3]);
        }
        if (Ch) {
            __nv_bfloat16 hv[32], lv[32];
#pragma unroll
            for (int c = 0; c < 32; c++) split2(v[c], hv[c], lv[c]);
            __nv_bfloat16* hrow = Ch + (size_t)row * ldc + n0 + cb;
            __nv_bfloat16* lrow = Cl + (size_t)row * ldc + n0 + cb;
#pragma unroll
            for (int c8 = 0; c8 < 4; c8++) {
                *(uint4*)(hrow + c8 * 8) = *(uint4*)&hv[c8 * 8];
                *(uint4*)(lrow + c8 * 8) = *(uint4*)&lv[c8 * 8];
            }
        }
    }
    TCGEN05_FENCE_BEFORE();
    __syncthreads();
    if (tid == 0) { MBARRIER_INVAL(sb + 8); }
    __syncthreads();
    if (wid == 0) { TCGEN05_DEALLOC(tmem, 256); }

#else  // ---------------- FMA fallback (same launch config) ----------------
    float* As = (float*)smem;                 // [16][68]
    float* Bs = (float*)smem + 16 * 68;       // [16][132]
    const int tx = tid & 15, ty = tid >> 4;   // 16 x 8

    for (int half = 0; half < 4; half++) {
        const int mq = half >> 1, nq = half & 1;
        const int mbase = m0 + mq * 64;
        const int nbase = n0 + nq * 128;
        float acc[8][8];
#pragma unroll
        for (int i = 0; i < 8; i++)
#pragma unroll
            for (int j = 0; j < 8; j++) acc[i][j] = 0.0f;

        for (int k0 = 0; k0 < K; k0 += 16) {
#pragma unroll
            for (int it = 0; it < 8; it++) {
                int i = tid + it * 128;
                int row = i >> 4, kk = i & 15;
                size_t idx = (size_t)(mbase + row) * lda + k0 + kk;
                As[kk * 68 + row] = __bfloat162float(Ah[idx]) + __bfloat162float(Al[idx]);
            }
#pragma unroll
            for (int it = 0; it < 16; it++) {
                int i = tid + it * 128;
                int row = i >> 4, kk = i & 15;
                size_t idx = (size_t)(nbase + row) * ldb + k0 + kk;
                Bs[kk * 132 + row] = __bfloat162float(Bh[idx]) + __bfloat162float(Bl[idx]);
            }
            __syncthreads();
#pragma unroll
            for (int kk = 0; kk < 16; kk++) {
                float a[8], b[8];
#pragma unroll
                for (int u = 0; u < 8; u++) a[u] = As[kk * 68 + ty * 8 + u];
#pragma unroll
                for (int u = 0; u < 8; u++) b[u] = Bs[kk * 132 + tx * 8 + u];
#pragma unroll
                for (int i = 0; i < 8; i++)
#pragma unroll
                    for (int j = 0; j < 8; j++)
                        acc[i][j] = fmaf(a[i], b[j], acc[i][j]);
            }
            __syncthreads();
        }

        float bv[8];
#pragma unroll
        for (int j = 0; j < 8; j++) bv[j] = bias ? bias[nbase + tx * 8 + j] : 0.0f;
#pragma unroll
        for (int i = 0; i < 8; i++) {
            int r = mbase + ty * 8 + i;
            float v[8];
#pragma unroll
            for (int j = 0; j < 8; j++) v[j] = scale * (acc[i][j] + bv[j]);
            float* crow = C + (size_t)r * ldc + nbase + tx * 8;
            *(float4*)(crow + 0) = make_float4(v[0], v[1], v[2], v[3]);
            *(float4*)(crow + 4) = make_float4(v[4], v[5], v[6], v[7]);
            if (Ch) {
                __nv_bfloat16 hv[8], lv[8];
#pragma unroll
                for (int j = 0; j < 8; j++) split2(v[j], hv[j], lv[j]);
                *(uint4*)(Ch + (size_t)r * ldc + nbase + tx * 8) = *(uint4*)hv;
                *(uint4*)(Cl + (size_t)r * ldc + nbase + tx * 8) = *(uint4*)lv;
            }
        }
        __syncthreads();
    }
#endif
}

// ================= attention kernels =================
__global__ __launch_bounds__(256)
void chunk_kv_kernel()
{
    __shared__ float Ks[16][TP];
    __shared__ float Vs[16][TP];
    const int c = blockIdx.x, h = blockIdx.y, b = blockIdx.z;
    const int tid = threadIdx.x;
    const int tx = tid & 15, ty = tid >> 4;
    const float s = head_slope(h);

    const float* kbase = g_ke  + ((size_t)(b * SEQ + c * CHUNKL)) * DMODEL + h * DHEAD;
    const float* vbase = g_qkv + ((size_t)(b * SEQ + c * CHUNKL)) * NQKV  + 4096 + h * DHEAD;

    float acc[8][8];
#pragma unroll
    for (int i = 0; i < 8; i++)
#pragma unroll
        for (int j = 0; j < 8; j++) acc[i][j] = 0.0f;

    for (int j0 = 0; j0 < CHUNKL; j0 += 16) {
#pragma unroll
        for (int it = 0; it < 2; it++) {
            int f   = tid + it * 256;
            int row = f >> 5;
            int c4  = (f & 31) * 4;
            int j   = j0 + row;
            float kd = expf(-s * (float)(CHUNKL - 1 - j));
            float4 kv = *(const float4*)(kbase + (size_t)j * DMODEL + c4);
            kv.x *= kd; kv.y *= kd; kv.z *= kd; kv.w *= kd;
            *(float4*)&Ks[row][c4] = kv;
            float4 vv = *(const float4*)(vbase + (size_t)j * NQKV + c4);
            *(float4*)&Vs[row][c4] = vv;
        }
        __syncthreads();
#pragma unroll
        for (int kk = 0; kk < 16; kk++) {
            float a[8], bb[8];
#pragma unroll
            for (int u = 0; u < 8; u++) a[u]  = Ks[kk][ty * 8 + u];
#pragma unroll
            for (int u = 0; u < 8; u++) bb[u] = Vs[kk][tx * 8 + u];
#pragma unroll
            for (int i = 0; i < 8; i++)
#pragma unroll
                for (int j = 0; j < 8; j++)
                    acc[i][j] = fmaf(a[i], bb[j], acc[i][j]);
        }
        __syncthreads();
    }

    float* gout = g_st + ((size_t)((b * NHEAD + h) * NCHUNK + c)) * (128 * 128);
#pragma unroll
    for (int i = 0; i < 8; i++) {
        float* row = gout + (size_t)(ty * 8 + i) * 128 + tx * 8;
        *(float4*)(row + 0) = make_float4(acc[i][0], acc[i][1], acc[i][2], acc[i][3]);
        *(float4*)(row + 4) = make_float4(acc[i][4], acc[i][5], acc[i][6], acc[i][7]);
    }
}

__global__ __launch_bounds__(256)
void scan_kernel()
{
    const int bh = blockIdx.y;
    const int h  = bh & (NHEAD - 1);
    const float s   = head_slope(h);
    const float lam = expf(-s * (float)CHUNKL);
    const int e = blockIdx.x * 256 + threadIdx.x;
    float* base = g_st + (size_t)bh * NCHUNK * (128 * 128) + e;
    float S = 0.0f;
#pragma unroll 4
    for (int c = 0; c < NCHUNK; c++) {
        float g = base[(size_t)c * (128 * 128)];
        base[(size_t)c * (128 * 128)] = S;
        S = fmaf(lam, S, g);
    }
}

__global__ __launch_bounds__(256)
void chunk_out_kernel()
{
    extern __shared__ float sm[];
    float* Ash = sm;
    float* T1  = sm + 128 * APITCH;
    float* T2  = T1 + 16 * TP;

    const int c = blockIdx.x, hh = blockIdx.y, b = blockIdx.z;
    const int tid = threadIdx.x;
    const int tx = tid & 15, ty = tid >> 4;
    const float s = head_slope(hh);

    const size_t tok0 = (size_t)(b * SEQ + c * CHUNKL);
    const float* qbase = g_qe  + tok0 * DMODEL + hh * DHEAD;
    const float* kbase = g_ke  + tok0 * DMODEL + hh * DHEAD;
    const float* vbase = g_qkv + tok0 * NQKV  + 4096 + hh * DHEAD;
    const float* Sbase = g_st  + ((size_t)((b * NHEAD + hh) * NCHUNK + c)) * (128 * 128);

    float acc[8][8];
#pragma unroll
    for (int i = 0; i < 8; i++)
#pragma unroll
        for (int j = 0; j < 8; j++) acc[i][j] = 0.0f;

    for (int d0 = 0; d0 < DHEAD; d0 += 16) {
#pragma unroll
        for (int it = 0; it < 2; it++) {
            int f   = tid + it * 256;
            int row = f >> 2;
            int kq  = (f & 3) * 4;
            float4 qv = *(const float4*)(qbase + (size_t)row * DMODEL + d0 + kq);
            T1[(kq + 0) * TP + row] = qv.x; T1[(kq + 1) * TP + row] = qv.y;
            T1[(kq + 2) * TP + row] = qv.z; T1[(kq + 3) * TP + row] = qv.w;
            float4 kv = *(const float4*)(kbase + (size_t)row * DMODEL + d0 + kq);
            T2[(kq + 0) * TP + row] = kv.x; T2[(kq + 1) * TP + row] = kv.y;
            T2[(kq + 2) * TP + row] = kv.z; T2[(kq + 3) * TP + row] = kv.w;
        }
        __syncthreads();
#pragma unroll
        for (int kk = 0; kk < 16; kk++) {
            float a[8], bb[8];
#pragma unroll
            for (int u = 0; u < 8; u++) a[u]  = T1[kk * TP + ty * 8 + u];
#pragma unroll
            for (int u = 0; u < 8; u++) bb[u] = T2[kk * TP + tx * 8 + u];
#pragma unroll
            for (int i = 0; i < 8; i++)
#pragma unroll
                for (int j = 0; j < 8; j++)
                    acc[i][j] = fmaf(a[i], bb[j], acc[i][j]);
        }
        __syncthreads();
    }

#pragma unroll
    for (int jj = 0; jj < 8; jj++) {
#pragma unroll
        for (int ii = 0; ii < 8; ii++) {
            int i = ty * 8 + ii, j = tx * 8 + jj;
            float v = (i >= j) ? acc[ii][jj] * expf(-s * (float)(i - j)) : 0.0f;
            Ash[j * APITCH + i] = v;
        }
    }
    __syncthreads();

    float accO[8][8];
#pragma unroll
    for (int i = 0; i < 8; i++)
#pragma unroll
        for (int j = 0; j < 8; j++) accO[i][j] = 0.0f;

    for (int j0 = 0; j0 < CHUNKL; j0 += 16) {
#pragma unroll
        for (int it = 0; it < 2; it++) {
            int f   = tid + it * 256;
            int row = f >> 5;
            int c4  = (f & 31) * 4;
            float4 vv = *(const float4*)(vbase + (size_t)(j0 + row) * NQKV + c4);
            *(float4*)&T1[row * TP + c4] = vv;
        }
        __syncthreads();
#pragma unroll
        for (int kk = 0; kk < 16; kk++) {
            float a[8], bb[8];
#pragma unroll
            for (int u = 0; u < 8; u++) a[u]  = Ash[(j0 + kk) * APITCH + ty * 8 + u];
#pragma unroll
            for (int u = 0; u < 8; u++) bb[u] = T1[kk * TP + tx * 8 + u];
#pragma unroll
            for (int i = 0; i < 8; i++)
#pragma unroll
                for (int j = 0; j < 8; j++)
                    accO[i][j] = fmaf(a[i], bb[j], accO[i][j]);
        }
        __syncthreads();
    }

    float acc2[8][8];
#pragma unroll
    for (int i = 0; i < 8; i++)
#pragma unroll
        for (int j = 0; j < 8; j++) acc2[i][j] = 0.0f;

    for (int d0 = 0; d0 < DHEAD; d0 += 16) {
#pragma unroll
        for (int it = 0; it < 2; it++) {
            int f   = tid + it * 256;
            int row = f >> 2;
            int kq  = (f & 3) * 4;
            float4 qv = *(const float4*)(qbase + (size_t)row * DMODEL + d0 + kq);
            T1[(kq + 0) * TP + row] = qv.x; T1[(kq + 1) * TP + row] = qv.y;
            T1[(kq + 2) * TP + row] = qv.z; T1[(kq + 3) * TP + row] = qv.w;
        }
#pragma unroll
        for (int it = 0; it < 2; it++) {
            int f   = tid + it * 256;
            int row = f >> 5;
            int c4  = (f & 31) * 4;
            float4 sv = *(const float4*)(Sbase + (size_t)(d0 + row) * 128 + c4);
            *(float4*)&T2[row * TP + c4] = sv;
        }
        __syncthreads();
#pragma unroll
        for (int kk = 0; kk < 16; kk++) {
            float a[8], bb[8];
#pragma unroll
            for (int u = 0; u < 8; u++) a[u]  = T1[kk * TP + ty * 8 + u];
#pragma unroll
            for (int u = 0; u < 8; u++) bb[u] = T2[kk * TP + tx * 8 + u];
#pragma unroll
            for (int i = 0; i < 8; i++)
#pragma unroll
                for (int j = 0; j < 8; j++)
                    acc2[i][j] = fmaf(a[i], bb[j], acc2[i][j]);
        }
        __syncthreads();
    }

    float vals[8][8];
#pragma unroll
    for (int ii = 0; ii < 8; ii++) {
        float qd = expf(-s * (float)(ty * 8 + ii + 1));
#pragma unroll
        for (int jj = 0; jj < 8; jj++)
            vals[ii][jj] = accO[ii][jj] + qd * acc2[ii][jj];
    }

#pragma unroll
    for (int ii = 0; ii < 8; ii++) {
        float ps = 0.0f, pq = 0.0f;
#pragma unroll
        for (int jj = 0; jj < 8; jj++) { float v = vals[ii][jj]; ps += v; pq += v * v; }
        T1[(ty * 8 + ii) * 16 + tx] = ps;
        T2[(ty * 8 + ii) * 16 + tx] = pq;
    }
    __syncthreads();

    if (tid < 128) {
        float s1 = 0.0f, s2 = 0.0f;
#pragma unroll
        for (int t = 0; t < 16; t++) { s1 += T1[tid * 16 + t]; s2 += T2[tid * 16 + t]; }
        float mu  = s1 * (1.0f / 128.0f);
        float var = s2 * (1.0f / 128.0f) - mu * mu;
        Ash[tid]       = mu;
        Ash[128 + tid] = rsqrtf(var + 1e-5f);
    }
    __syncthreads();

    float* obase = g_y + tok0 * DMODEL + hh * DHEAD;
    __nv_bfloat16* ohbase = g_y_h + tok0 * DMODEL + hh * DHEAD;
    __nv_bfloat16* olbase = g_y_l + tok0 * DMODEL + hh * DHEAD;
#pragma unroll
    for (int ii = 0; ii < 8; ii++) {
        int i = ty * 8 + ii;
        float mu = Ash[i], rs = Ash[128 + i];
        float o[8];
#pragma unroll
        for (int jj = 0; jj < 8; jj++) o[jj] = (vals[ii][jj] - mu) * rs;
        float* row = obase + (size_t)i * DMODEL + tx * 8;
        *(float4*)(row + 0) = make_float4(o[0], o[1], o[2], o[3]);
        *(float4*)(row + 4) = make_float4(o[4], o[5], o[6], o[7]);
        __nv_bfloat16 hv[8], lv[8];
#pragma unroll
        for (int jj = 0; jj < 8; jj++) split2(o[jj], hv[jj], lv[jj]);
        *(uint4*)(ohbase + (size_t)i * DMODEL + tx * 8) = *(uint4*)hv;
        *(uint4*)(olbase + (size_t)i * DMODEL + tx * 8) = *(uint4*)lv;
    }
}

// ================= host launcher =================
extern "C" void kernel_launch(void* const* d_in, const int* in_sizes, int n_in,
                              void* d_out, int out_size)
{
    (void)in_sizes; (void)n_in; (void)out_size;
    const float* x       = (const float*)d_in[0];
    const float* W_in    = (const float*)d_in[1];
    const float* W_embed = (const float*)d_in[2];
    const float* b_embed = (const float*)d_in[3];
    const float* W_out   = (const float*)d_in[4];
    float* out = (float*)d_out;

    float *qkv, *qe, *ke;
    __nv_bfloat16 *qkv_h, *qkv_l, *x_h, *x_l, *win_h, *win_l, *wemb_h, *wemb_l, *wout_h, *wout_l, *y_h, *y_l;
    cudaGetSymbolAddress((void**)&qkv,   g_qkv);
    cudaGetSymbolAddress((void**)&qe,    g_qe);
    cudaGetSymbolAddress((void**)&ke,    g_ke);
    cudaGetSymbolAddress((void**)&qkv_h, g_qkv_h);
    cudaGetSymbolAddress((void**)&qkv_l, g_qkv_l);
    cudaGetSymbolAddress((void**)&x_h,   g_x_h);
    cudaGetSymbolAddress((void**)&x_l,   g_x_l);
    cudaGetSymbolAddress((void**)&win_h, g_win_h);
    cudaGetSymbolAddress((void**)&win_l, g_win_l);
    cudaGetSymbolAddress((void**)&wemb_h,g_wemb_h);
    cudaGetSymbolAddress((void**)&wemb_l,g_wemb_l);
    cudaGetSymbolAddress((void**)&wout_h,g_wout_h);
    cudaGetSymbolAddress((void**)&wout_l,g_wout_l);
    cudaGetSymbolAddress((void**)&y_h,   g_y_h);
    cudaGetSymbolAddress((void**)&y_l,   g_y_l);
    float* y; cudaGetSymbolAddress((void**)&y, g_y);

    const int smem_k5 = (128 * APITCH + 2 * 16 * TP) * 4;
    cudaFuncSetAttribute(chunk_out_kernel, cudaFuncAttributeMaxDynamicSharedMemorySize, smem_k5);
    cudaFuncSetAttribute(gemm_tc_kernel, cudaFuncAttributeMaxDynamicSharedMemorySize, GEMM_SMEM);

    // splits
    {
        long long n4;
        n4 = (long long)NTOK * DMODEL / 4;
        split_kernel<<<(unsigned)((n4 + 255) / 256), 256>>>(x, x_h, x_l, n4);
        n4 = (long long)NQKV * DMODEL / 4;
        split_kernel<<<(unsigned)((n4 + 255) / 256), 256>>>(W_in, win_h, win_l, n4);
        n4 = (long long)DMODEL * DMODEL / 4;
        split_kernel<<<(unsigned)((n4 + 255) / 256), 256>>>(W_embed, wemb_h, wemb_l, n4);
        split_kernel<<<(unsigned)((n4 + 255) / 256), 256>>>(W_out, wout_h, wout_l, n4);
    }

    // 1) qkv = x @ W_in^T  (+ bf16 split output)
    gemm_tc_kernel<<<dim3(NQKV / 256, NTOK / 128), 128, GEMM_SMEM>>>(
        x_h, x_l, DMODEL, win_h, win_l, DMODEL,
        qkv, qkv_h, qkv_l, NQKV, DMODEL, nullptr, 1.0f);

    // 2) qe = qkv[:,0:2048] @ W_embed^T + b
    gemm_tc_kernel<<<dim3(DMODEL / 256, NTOK / 128), 128, GEMM_SMEM>>>(
        qkv_h, qkv_l, NQKV, wemb_h, wemb_l, DMODEL,
        qe, nullptr, nullptr, DMODEL, DMODEL, b_embed, 1.0f);

    // 3) ke = (qkv[:,2048:4096] @ W_embed^T + b) * QK_SCALE
    gemm_tc_kernel<<<dim3(DMODEL / 256, NTOK / 128), 128, GEMM_SMEM>>>(
        qkv_h + 2048, qkv_l + 2048, NQKV, wemb_h, wemb_l, DMODEL,
        ke, nullptr, nullptr, DMODEL, DMODEL, b_embed, QK_SCALE);

    // 4) per-chunk KV products
    chunk_kv_kernel<<<dim3(NCHUNK, NHEAD, BATCH), 256>>>();

    // 5) state scan
    scan_kernel<<<dim3(128 * 128 / 256, BATCH * NHEAD), 256>>>();

    // 6) per-chunk output + fused LayerNorm (+ bf16 split of y)
    chunk_out_kernel<<<dim3(NCHUNK, NHEAD, BATCH), 256, smem_k5>>>();

    // 7) out = y @ W_out^T
    gemm_tc_kernel<<<dim3(DMODEL / 256, NTOK / 128), 128, GEMM_SMEM>>>(
        y_h, y_l, DMODEL, wout_h, wout_l, DMODEL,
        out, nullptr, nullptr, DMODEL, DMODEL, nullptr, 1.0f);
}

// round 10
// speedup vs baseline: 2.2773x; 2.2773x over previous
#include <cuda_runtime.h>
#include <cuda_bf16.h>
#include <math.h>
#include <stdint.h>

// ---------------- problem constants ----------------
#define BATCH   2
#define SEQ     8192
#define NTOK    (BATCH*SEQ)        // 16384
#define DMODEL  2048
#define NQKV    6144
#define NHEAD   16
#define DHEAD   128
#define NCHUNK  64
#define CHUNKL  128
#define QK_SCALE 0.08838834764831845f

#define TP 132
#define APITCH 129

// tcgen05 is only legal on arch-specific / family-specific targets.
#if defined(__CUDA_ARCH__) && (defined(__CUDA_ARCH_FEAT_SM103_ALL) || defined(__CUDA_ARCH_FEAT_SM100_ALL) || defined(__CUDA_ARCH_FEAT_SM101_ALL) || defined(__CUDA_ARCH_FAMILY_SPECIFIC__) || defined(__CUDA_ARCH_SPECIFIC__))
#define HAS_TC 1
#else
#define HAS_TC 0
#endif

// ---------------- device scratch ----------------
__device__ float g_qkv[(size_t)NTOK * NQKV];
__device__ __nv_bfloat16 g_qkv_h[(size_t)NTOK * NQKV];
__device__ __nv_bfloat16 g_qkv_l[(size_t)NTOK * NQKV];
__device__ float g_qe [(size_t)NTOK * DMODEL];
__device__ float g_ke [(size_t)NTOK * DMODEL];
__device__ float g_st [(size_t)BATCH * NHEAD * NCHUNK * 128 * 128];
__device__ float g_y  [(size_t)NTOK * DMODEL];
__device__ __nv_bfloat16 g_y_h[(size_t)NTOK * DMODEL];
__device__ __nv_bfloat16 g_y_l[(size_t)NTOK * DMODEL];
__device__ __nv_bfloat16 g_x_h[(size_t)NTOK * DMODEL];
__device__ __nv_bfloat16 g_x_l[(size_t)NTOK * DMODEL];
__device__ __nv_bfloat16 g_win_h[(size_t)NQKV * DMODEL];
__device__ __nv_bfloat16 g_win_l[(size_t)NQKV * DMODEL];
__device__ __nv_bfloat16 g_wemb_h[(size_t)DMODEL * DMODEL];
__device__ __nv_bfloat16 g_wemb_l[(size_t)DMODEL * DMODEL];
__device__ __nv_bfloat16 g_wout_h[(size_t)DMODEL * DMODEL];
__device__ __nv_bfloat16 g_wout_l[(size_t)DMODEL * DMODEL];

__device__ __forceinline__ float head_slope(int h) {
    return -logf(1.0f - exp2f(-5.0f - (float)h));
}

__device__ __forceinline__ void split2(float v, __nv_bfloat16& h, __nv_bfloat16& l) {
    h = __float2bfloat16_rn(v);
    l = __float2bfloat16_rn(v - __bfloat162float(h));
}

// ================= PTX helpers =================
__device__ __forceinline__ uint32_t smem_to_u32(const void* p) {
    uint32_t a;
    asm("{ .reg .u64 t; cvta.to.shared.u64 t, %1; cvt.u32.u64 %0, t; }" : "=r"(a) : "l"(p));
    return a;
}
#define MBARRIER_INIT(mbar, count) \
    asm volatile("mbarrier.init.shared.b64 [%0], %1;" \
        :: "r"((uint32_t)(mbar)), "r"((uint32_t)(count)) : "memory")
#define MBARRIER_INVAL(mbar) \
    asm volatile("mbarrier.inval.shared.b64 [%0];" \
        :: "r"((uint32_t)(mbar)) : "memory")
#define MBARRIER_WAIT_PARITY(mbar_smem_addr, phase_parity) do { \
    uint32_t _mbar = (uint32_t)(mbar_smem_addr); \
    uint32_t _parity = (uint32_t)(phase_parity); \
    uint32_t _done; \
    asm volatile( \
        "{\n\t.reg .pred p;\n\t" \
        "mbarrier.try_wait.parity.acquire.cta.shared::cta.b64 p, [%1], %2;\n\t" \
        "selp.b32 %0, 1, 0, p;\n\t}" \
        : "=r"(_done) : "r"(_mbar), "r"(_parity) : "memory"); \
    if (!_done) { \
        asm volatile( \
            "{\n\t.reg .pred P1;\n\t" \
            "WAIT_LOOP_%=:\n\t" \
            "mbarrier.try_wait.parity.acquire.cta.shared::cta.b64 P1, [%0], %1, 0x989680;\n\t" \
            "@P1 bra.uni WAIT_DONE_%=;\n\t" \
            "bra.uni WAIT_LOOP_%=;\n\t" \
            "WAIT_DONE_%=:\n\t}" \
            :: "r"(_mbar), "r"(_parity) : "memory"); \
    } \
} while(0)
#define FENCE_PROXY_ASYNC_SHARED_CTA() \
    asm volatile("fence.proxy.async.shared::cta;" ::: "memory")

#if HAS_TC
__device__ __forceinline__ uint32_t elect_one_pred() {
    uint32_t pred;
    asm volatile(
        "{\n\t.reg .pred p;\n\t"
        "elect.sync _|p, 0xFFFFFFFF;\n\t"
        "selp.b32 %0, 1, 0, p;\n\t}"
        : "=r"(pred));
    return pred;
}
#define TCGEN05_ALLOC(smem_result_addr, nCols) \
    asm volatile("tcgen05.alloc.cta_group::1.sync.aligned.shared::cta.b32 [%0], %1;" \
        :: "r"((uint32_t)(smem_result_addr)), "r"((uint32_t)(nCols)) : "memory")
#define TCGEN05_DEALLOC(tmem_addr, nCols) \
    asm volatile("tcgen05.dealloc.cta_group::1.sync.aligned.b32 %0, %1;" \
        :: "r"(tmem_addr), "r"((uint32_t)(nCols)))
#define TCGEN05_COMMIT(mbar) \
    asm volatile("tcgen05.commit.cta_group::1.mbarrier::arrive::one.shared::cluster.b64 [%0];" \
        :: "r"((uint32_t)(mbar)) : "memory")
#define TCGEN05_FENCE_AFTER() \
    asm volatile("tcgen05.fence::after_thread_sync;" ::: "memory")
#define TCGEN05_FENCE_BEFORE() \
    asm volatile("tcgen05.fence::before_thread_sync;" ::: "memory")
#define TCGEN05_WAIT_LD() \
    asm volatile("tcgen05.wait::ld.sync.aligned;" ::: "memory")
#define TCGEN05_LD_32X32B_X32(r, tmem_addr) \
    asm volatile( \
        "tcgen05.ld.sync.aligned.32x32b.x32.b32 " \
        "{%0, %1, %2, %3, %4, %5, %6, %7, " \
        " %8, %9, %10, %11, %12, %13, %14, %15, " \
        " %16, %17, %18, %19, %20, %21, %22, %23, " \
        " %24, %25, %26, %27, %28, %29, %30, %31}, [%32];" \
        : "=r"((r)[0]),  "=r"((r)[1]),  "=r"((r)[2]),  "=r"((r)[3]), \
          "=r"((r)[4]),  "=r"((r)[5]),  "=r"((r)[6]),  "=r"((r)[7]), \
          "=r"((r)[8]),  "=r"((r)[9]),  "=r"((r)[10]), "=r"((r)[11]), \
          "=r"((r)[12]), "=r"((r)[13]), "=r"((r)[14]), "=r"((r)[15]), \
          "=r"((r)[16]), "=r"((r)[17]), "=r"((r)[18]), "=r"((r)[19]), \
          "=r"((r)[20]), "=r"((r)[21]), "=r"((r)[22]), "=r"((r)[23]), \
          "=r"((r)[24]), "=r"((r)[25]), "=r"((r)[26]), "=r"((r)[27]), \
          "=r"((r)[28]), "=r"((r)[29]), "=r"((r)[30]), "=r"((r)[31]) \
        : "r"(tmem_addr))

static constexpr uint64_t SMEM_DESC_BASE_SW128 =
    (uint64_t(2)  << 61) | (uint64_t(1) << 46) | (uint64_t(64) << 32) | (uint64_t(1) << 16);
#define MAKE_SMEM_DESC(base_addr) \
    (SMEM_DESC_BASE_SW128 | ((uint64_t)((base_addr) >> 4) & 0x3FFF))

// idesc: dtype=F32, atype=BF16, btype=BF16, K-major/K-major, M=128, N=64
#define IDESC_M128N64 ((1u<<4)|(1u<<7)|(1u<<10)|((64u/8u)<<17)|((128u/16u)<<24))

__device__ __forceinline__ void mma_f16_ss(uint32_t d_tmem, uint64_t a_desc,
                                           uint64_t b_desc, uint32_t idesc, bool acc) {
    uint32_t en = acc ? 1u : 0u;
    asm volatile(
        "{\n\t.reg .pred p;\n\t"
        "setp.ne.u32 p, %5, 0;\n\t"
        "tcgen05.mma.cta_group::1.kind::f16 [%0], %1, %2, %3, {%4, %4, %4, %4}, p;\n\t}"
        :: "r"(d_tmem), "l"(a_desc), "l"(b_desc), "r"(idesc), "r"(0u), "r"(en)
        : "memory");
}
#endif // HAS_TC

#define SWZ128(off) ((off) ^ (((off) >> 3) & 0x70))

// ================= fp32 -> (hi,lo) bf16 split =================
__global__ __launch_bounds__(256)
void split_kernel(const float* __restrict__ in, __nv_bfloat16* __restrict__ hi,
                  __nv_bfloat16* __restrict__ lo, long long n4)
{
    long long i = (long long)blockIdx.x * 256 + threadIdx.x;
    if (i >= n4) return;
    float4 v = ((const float4*)in)[i];
    __nv_bfloat16 h0,h1,h2,h3,l0,l1,l2,l3;
    split2(v.x,h0,l0); split2(v.y,h1,l1); split2(v.z,h2,l2); split2(v.w,h3,l3);
    __nv_bfloat162* hp = (__nv_bfloat162*)(hi + 4*i);
    __nv_bfloat162* lp = (__nv_bfloat162*)(lo + 4*i);
    hp[0] = __nv_bfloat162(h0,h1); hp[1] = __nv_bfloat162(h2,h3);
    lp[0] = __nv_bfloat162(l0,l1); lp[1] = __nv_bfloat162(l2,l3);
}

// ================= GEMM: tcgen05 bf16x3, double-buffered =================
// C[m,n] = scale*(sum_k A[m,k]*B[n,k] + bias[n]); tile 128(M) x 256(N), KT=64.
#define KT 64
#define STAGE_BYTES 98304
#define SMEM_TILE0 1024
#define GEMM_SMEM (SMEM_TILE0 + 2*STAGE_BYTES)   // 197632

__global__ __launch_bounds__(256) __cluster_dims__(1, 1, 1)
void gemm_tc_kernel(const __nv_bfloat16* __restrict__ Ah, const __nv_bfloat16* __restrict__ Al, int lda,
                    const __nv_bfloat16* __restrict__ Bh, const __nv_bfloat16* __restrict__ Bl, int ldb,
                    float* __restrict__ C, __nv_bfloat16* __restrict__ Ch, __nv_bfloat16* __restrict__ Cl,
                    int ldc, int K, const float* __restrict__ bias, float scale)
{
    extern __shared__ __align__(1024) char smem[];
    const int tid = threadIdx.x;
    const int n0 = blockIdx.x * 256;
    const int m0 = blockIdx.y * 128;

#if HAS_TC
    const uint32_t sb = smem_to_u32(smem);
    const int wid = tid >> 5, lid = tid & 31;

    // warp 0 allocates TMEM; nobody relinquishes (avoids relinquish-before-alloc race)
    if (wid == 0) { TCGEN05_ALLOC(sb + 0, 256); }
    if (tid == 0) { MBARRIER_INIT(sb + 8, 1); MBARRIER_INIT(sb + 16, 1); }
    __syncthreads();
    uint32_t tmem;
    asm volatile("ld.shared.b32 %0, [%1];" : "=r"(tmem) : "r"(sb));

    const int ktiles = K / KT;

    for (int t = 0; t < ktiles; t++) {
        const int buf = t & 1;
        // buffer reuse: wait for tile t-2's MMAs (same buffer) to finish
        if (t >= 2) {
            MBARRIER_WAIT_PARITY(sb + 8 + buf * 8, ((t - 2) >> 1) & 1);
        }
        char* st = smem + SMEM_TILE0 + buf * STAGE_BYTES;
        const int k0 = t * KT;
        // A hi/lo: 128 rows x 128B (SW128); 1024 uint4 each, 4 per thread
#pragma unroll
        for (int it = 0; it < 4; it++) {
            int i = tid + it * 256;
            int row = i >> 3, c = i & 7;
            uint32_t sw = SWZ128((uint32_t)(row * 128 + c * 16));
            *(uint4*)(st + sw)         = *(const uint4*)(Ah + (size_t)(m0 + row) * lda + k0 + c * 8);
            *(uint4*)(st + 16384 + sw) = *(const uint4*)(Al + (size_t)(m0 + row) * lda + k0 + c * 8);
        }
        // B hi/lo: 256 rows x 128B (SW128); 2048 uint4 each, 8 per thread
#pragma unroll
        for (int it = 0; it < 8; it++) {
            int i = tid + it * 256;
            int row = i >> 3, c = i & 7;
            uint32_t sw = SWZ128((uint32_t)(row * 128 + c * 16));
            *(uint4*)(st + 32768 + sw) = *(const uint4*)(Bh + (size_t)(n0 + row) * ldb + k0 + c * 8);
            *(uint4*)(st + 65536 + sw) = *(const uint4*)(Bl + (size_t)(n0 + row) * ldb + k0 + c * 8);
        }
        FENCE_PROXY_ASYNC_SHARED_CTA();
        __syncthreads();

        if (wid == 0 && elect_one_pred()) {
            uint32_t sbase = sb + SMEM_TILE0 + buf * STAGE_BYTES;
            uint64_t dAh = MAKE_SMEM_DESC(sbase);
            uint64_t dAl = MAKE_SMEM_DESC(sbase + 16384);
            uint64_t dBh = MAKE_SMEM_DESC(sbase + 32768);
            uint64_t dBl = MAKE_SMEM_DESC(sbase + 65536);
#pragma unroll
            for (int ks = 0; ks < 4; ks++) {
                uint64_t oa = ks * 2;           // +32B per K-step (16B units)
#pragma unroll
                for (int p = 0; p < 3; p++) {
                    uint64_t da = (p == 2) ? dAl : dAh;
                    uint64_t db = (p == 1) ? dBl : dBh;
                    bool first = (t == 0 && ks == 0 && p == 0);
                    // nq innermost: consecutive MMAs hit 4 distinct accumulators
#pragma unroll
                    for (int nq = 0; nq < 4; nq++) {
                        uint32_t d = tmem + nq * 64;          // 64 fp32 cols per N-quarter
                        uint64_t ob = oa + nq * 512;          // +64 rows*128B = 512 units
                        mma_f16_ss(d, da + oa, db + ob, IDESC_M128N64, !first);
                    }
                }
            }
            TCGEN05_COMMIT(sb + 8 + buf * 8);
        }
        // no wait here: next iteration loads the OTHER buffer while these MMAs run
    }
    {
        uint32_t ph = (((uint32_t)ktiles >> 1) - 1) & 1;
        MBARRIER_WAIT_PARITY(sb + 8, ph);
        MBARRIER_WAIT_PARITY(sb + 16, ph);
    }
    TCGEN05_FENCE_AFTER();

    // epilogue: warp w: rows m0 + (w&3)*32 .. +31, cols (w>>2)*128 .. +127
    const int row = m0 + (wid & 3) * 32 + lid;
    const int colbase = (wid >> 2) * 128;
#pragma unroll
    for (int cq = 0; cq < 4; cq++) {
        const int cb = colbase + cq * 32;
        uint32_t regs[32];
        TCGEN05_LD_32X32B_X32(regs, tmem + cb);
        TCGEN05_WAIT_LD();
        float v[32];
#pragma unroll
        for (int c = 0; c < 32; c++) {
            float bv = bias ? bias[n0 + cb + c] : 0.0f;
            v[c] = scale * (__uint_as_float(regs[c]) + bv);
        }
        float* crow = C + (size_t)row * ldc + n0 + cb;
#pragma unroll
        for (int c4 = 0; c4 < 8; c4++) {
            *(float4*)(crow + c4 * 4) = make_float4(v[c4*4], v[c4*4+1], v[c4*4+2], v[c4*4+3]);
        }
        if (Ch) {
            __nv_bfloat16 hv[32], lv[32];
#pragma unroll
            for (int c = 0; c < 32; c++) split2(v[c], hv[c], lv[c]);
            __nv_bfloat16* hrow = Ch + (size_t)row * ldc + n0 + cb;
            __nv_bfloat16* lrow = Cl + (size_t)row * ldc + n0 + cb;
#pragma unroll
            for (int c8 = 0; c8 < 4; c8++) {
                *(uint4*)(hrow + c8 * 8) = *(uint4*)&hv[c8 * 8];
                *(uint4*)(lrow + c8 * 8) = *(uint4*)&lv[c8 * 8];
            }
        }
    }
    TCGEN05_FENCE_BEFORE();
    __syncthreads();
    if (tid == 0) { MBARRIER_INVAL(sb + 8); MBARRIER_INVAL(sb + 16); }
    __syncthreads();
    if (wid == 0) { TCGEN05_DEALLOC(tmem, 256); }

#else  // ---------------- FMA fallback (256 threads; correctness-only path) ----------------
    (void)smem;
    const int tx = tid & 15, ty = tid >> 4;   // 16 x 16

    for (int half = 0; half < 2; half++) {
        const int nbase = n0 + half * 128;
        float acc[8][8];
#pragma unroll
        for (int i = 0; i < 8; i++)
#pragma unroll
            for (int j = 0; j < 8; j++) acc[i][j] = 0.0f;

        for (int k0 = 0; k0 < K; k0 += 16) {
#pragma unroll
            for (int kk = 0; kk < 16; kk++) {
                float a[8], b[8];
#pragma unroll
                for (int u = 0; u < 8; u++) {
                    size_t ia = (size_t)(m0 + ty * 8 + u) * lda + k0 + kk;
                    a[u] = __bfloat162float(Ah[ia]) + __bfloat162float(Al[ia]);
                }
#pragma unroll
                for (int u = 0; u < 8; u++) {
                    size_t ib = (size_t)(nbase + tx * 8 + u) * ldb + k0 + kk;
                    b[u] = __bfloat162float(Bh[ib]) + __bfloat162float(Bl[ib]);
                }
#pragma unroll
                for (int i = 0; i < 8; i++)
#pragma unroll
                    for (int j = 0; j < 8; j++)
                        acc[i][j] = fmaf(a[i], b[j], acc[i][j]);
            }
        }

        float bv[8];
#pragma unroll
        for (int j = 0; j < 8; j++) bv[j] = bias ? bias[nbase + tx * 8 + j] : 0.0f;
#pragma unroll
        for (int i = 0; i < 8; i++) {
            int r = m0 + ty * 8 + i;
            float v[8];
#pragma unroll
            for (int j = 0; j < 8; j++) v[j] = scale * (acc[i][j] + bv[j]);
            float* crow = C + (size_t)r * ldc + nbase + tx * 8;
            *(float4*)(crow + 0) = make_float4(v[0], v[1], v[2], v[3]);
            *(float4*)(crow + 4) = make_float4(v[4], v[5], v[6], v[7]);
            if (Ch) {
                __nv_bfloat16 hv[8], lv[8];
#pragma unroll
                for (int j = 0; j < 8; j++) split2(v[j], hv[j], lv[j]);
                *(uint4*)(Ch + (size_t)r * ldc + nbase + tx * 8) = *(uint4*)hv;
                *(uint4*)(Cl + (size_t)r * ldc + nbase + tx * 8) = *(uint4*)lv;
            }
        }
    }
#endif
}

// ================= attention kernels =================
__global__ __launch_bounds__(256)
void chunk_kv_kernel()
{
    __shared__ float Ks[16][TP];
    __shared__ float Vs[16][TP];
    const int c = blockIdx.x, h = blockIdx.y, b = blockIdx.z;
    const int tid = threadIdx.x;
    const int tx = tid & 15, ty = tid >> 4;
    const float s = head_slope(h);

    const float* kbase = g_ke  + ((size_t)(b * SEQ + c * CHUNKL)) * DMODEL + h * DHEAD;
    const float* vbase = g_qkv + ((size_t)(b * SEQ + c * CHUNKL)) * NQKV  + 4096 + h * DHEAD;

    float acc[8][8];
#pragma unroll
    for (int i = 0; i < 8; i++)
#pragma unroll
        for (int j = 0; j < 8; j++) acc[i][j] = 0.0f;

    for (int j0 = 0; j0 < CHUNKL; j0 += 16) {
#pragma unroll
        for (int it = 0; it < 2; it++) {
            int f   = tid + it * 256;
            int row = f >> 5;
            int c4  = (f & 31) * 4;
            int j   = j0 + row;
            float kd = expf(-s * (float)(CHUNKL - 1 - j));
            float4 kv = *(const float4*)(kbase + (size_t)j * DMODEL + c4);
            kv.x *= kd; kv.y *= kd; kv.z *= kd; kv.w *= kd;
            *(float4*)&Ks[row][c4] = kv;
            float4 vv = *(const float4*)(vbase + (size_t)j * NQKV + c4);
            *(float4*)&Vs[row][c4] = vv;
        }
        __syncthreads();
#pragma unroll
        for (int kk = 0; kk < 16; kk++) {
            float a[8], bb[8];
#pragma unroll
            for (int u = 0; u < 8; u++) a[u]  = Ks[kk][ty * 8 + u];
#pragma unroll
            for (int u = 0; u < 8; u++) bb[u] = Vs[kk][tx * 8 + u];
#pragma unroll
            for (int i = 0; i < 8; i++)
#pragma unroll
                for (int j = 0; j < 8; j++)
                    acc[i][j] = fmaf(a[i], bb[j], acc[i][j]);
        }
        __syncthreads();
    }

    float* gout = g_st + ((size_t)((b * NHEAD + h) * NCHUNK + c)) * (128 * 128);
#pragma unroll
    for (int i = 0; i < 8; i++) {
        float* row = gout + (size_t)(ty * 8 + i) * 128 + tx * 8;
        *(float4*)(row + 0) = make_float4(acc[i][0], acc[i][1], acc[i][2], acc[i][3]);
        *(float4*)(row + 4) = make_float4(acc[i][4], acc[i][5], acc[i][6], acc[i][7]);
    }
}

__global__ __launch_bounds__(256)
void scan_kernel()
{
    const int bh = blockIdx.y;
    const int h  = bh & (NHEAD - 1);
    const float s   = head_slope(h);
    const float lam = expf(-s * (float)CHUNKL);
    const int e = blockIdx.x * 256 + threadIdx.x;
    float* base = g_st + (size_t)bh * NCHUNK * (128 * 128) + e;
    float S = 0.0f;
#pragma unroll 4
    for (int c = 0; c < NCHUNK; c++) {
        float g = base[(size_t)c * (128 * 128)];
        base[(size_t)c * (128 * 128)] = S;
        S = fmaf(lam, S, g);
    }
}

__global__ __launch_bounds__(256)
void chunk_out_kernel()
{
    extern __shared__ float sm[];
    float* Ash = sm;
    float* T1  = sm + 128 * APITCH;
    float* T2  = T1 + 16 * TP;

    const int c = blockIdx.x, hh = blockIdx.y, b = blockIdx.z;
    const int tid = threadIdx.x;
    const int tx = tid & 15, ty = tid >> 4;
    const float s = head_slope(hh);

    const size_t tok0 = (size_t)(b * SEQ + c * CHUNKL);
    const float* qbase = g_qe  + tok0 * DMODEL + hh * DHEAD;
    const float* kbase = g_ke  + tok0 * DMODEL + hh * DHEAD;
    const float* vbase = g_qkv + tok0 * NQKV  + 4096 + hh * DHEAD;
    const float* Sbase = g_st  + ((size_t)((b * NHEAD + hh) * NCHUNK + c)) * (128 * 128);

    float acc[8][8];
#pragma unroll
    for (int i = 0; i < 8; i++)
#pragma unroll
        for (int j = 0; j < 8; j++) acc[i][j] = 0.0f;

    for (int d0 = 0; d0 < DHEAD; d0 += 16) {
#pragma unroll
        for (int it = 0; it < 2; it++) {
            int f   = tid + it * 256;
            int row = f >> 2;
            int kq  = (f & 3) * 4;
            float4 qv = *(const float4*)(qbase + (size_t)row * DMODEL + d0 + kq);
            T1[(kq + 0) * TP + row] = qv.x; T1[(kq + 1) * TP + row] = qv.y;
            T1[(kq + 2) * TP + row] = qv.z; T1[(kq + 3) * TP + row] = qv.w;
            float4 kv = *(const float4*)(kbase + (size_t)row * DMODEL + d0 + kq);
            T2[(kq + 0) * TP + row] = kv.x; T2[(kq + 1) * TP + row] = kv.y;
            T2[(kq + 2) * TP + row] = kv.z; T2[(kq + 3) * TP + row] = kv.w;
        }
        __syncthreads();
#pragma unroll
        for (int kk = 0; kk < 16; kk++) {
            float a[8], bb[8];
#pragma unroll
            for (int u = 0; u < 8; u++) a[u]  = T1[kk * TP + ty * 8 + u];
#pragma unroll
            for (int u = 0; u < 8; u++) bb[u] = T2[kk * TP + tx * 8 + u];
#pragma unroll
            for (int i = 0; i < 8; i++)
#pragma unroll
                for (int j = 0; j < 8; j++)
                    acc[i][j] = fmaf(a[i], bb[j], acc[i][j]);
        }
        __syncthreads();
    }

#pragma unroll
    for (int jj = 0; jj < 8; jj++) {
#pragma unroll
        for (int ii = 0; ii < 8; ii++) {
            int i = ty * 8 + ii, j = tx * 8 + jj;
            float v = (i >= j) ? acc[ii][jj] * expf(-s * (float)(i - j)) : 0.0f;
            Ash[j * APITCH + i] = v;
        }
    }
    __syncthreads();

    float accO[8][8];
#pragma unroll
    for (int i = 0; i < 8; i++)
#pragma unroll
        for (int j = 0; j < 8; j++) accO[i][j] = 0.0f;

    for (int j0 = 0; j0 < CHUNKL; j0 += 16) {
#pragma unroll
        for (int it = 0; it < 2; it++) {
            int f   = tid + it * 256;
            int row = f >> 5;
            int c4  = (f & 31) * 4;
            float4 vv = *(const float4*)(vbase + (size_t)(j0 + row) * NQKV + c4);
            *(float4*)&T1[row * TP + c4] = vv;
        }
        __syncthreads();
#pragma unroll
        for (int kk = 0; kk < 16; kk++) {
            float a[8], bb[8];
#pragma unroll
            for (int u = 0; u < 8; u++) a[u]  = Ash[(j0 + kk) * APITCH + ty * 8 + u];
#pragma unroll
            for (int u = 0; u < 8; u++) bb[u] = T1[kk * TP + tx * 8 + u];
#pragma unroll
            for (int i = 0; i < 8; i++)
#pragma unroll
                for (int j = 0; j < 8; j++)
                    accO[i][j] = fmaf(a[i], bb[j], accO[i][j]);
        }
        __syncthreads();
    }

    float acc2[8][8];
#pragma unroll
    for (int i = 0; i < 8; i++)
#pragma unroll
        for (int j = 0; j < 8; j++) acc2[i][j] = 0.0f;

    for (int d0 = 0; d0 < DHEAD; d0 += 16) {
#pragma unroll
        for (int it = 0; it < 2; it++) {
            int f   = tid + it * 256;
            int row = f >> 2;
            int kq  = (f & 3) * 4;
            float4 qv = *(const float4*)(qbase + (size_t)row * DMODEL + d0 + kq);
            T1[(kq + 0) * TP + row] = qv.x; T1[(kq + 1) * TP + row] = qv.y;
            T1[(kq + 2) * TP + row] = qv.z; T1[(kq + 3) * TP + row] = qv.w;
        }
#pragma unroll
        for (int it = 0; it < 2; it++) {
            int f   = tid + it * 256;
            int row = f >> 5;
            int c4  = (f & 31) * 4;
            float4 sv = *(const float4*)(Sbase + (size_t)(d0 + row) * 128 + c4);
            *(float4*)&T2[row * TP + c4] = sv;
        }
        __syncthreads();
#pragma unroll
        for (int kk = 0; kk < 16; kk++) {
            float a[8], bb[8];
#pragma unroll
            for (int u = 0; u < 8; u++) a[u]  = T1[kk * TP + ty * 8 + u];
#pragma unroll
            for (int u = 0; u < 8; u++) bb[u] = T2[kk * TP + tx * 8 + u];
#pragma unroll
            for (int i = 0; i < 8; i++)
#pragma unroll
                for (int j = 0; j < 8; j++)
                    acc2[i][j] = fmaf(a[i], bb[j], acc2[i][j]);
        }
        __syncthreads();
    }

    float vals[8][8];
#pragma unroll
    for (int ii = 0; ii < 8; ii++) {
        float qd = expf(-s * (float)(ty * 8 + ii + 1));
#pragma unroll
        for (int jj = 0; jj < 8; jj++)
            vals[ii][jj] = accO[ii][jj] + qd * acc2[ii][jj];
    }

#pragma unroll
    for (int ii = 0; ii < 8; ii++) {
        float ps = 0.0f, pq = 0.0f;
#pragma unroll
        for (int jj = 0; jj < 8; jj++) { float v = vals[ii][jj]; ps += v; pq += v * v; }
        T1[(ty * 8 + ii) * 16 + tx] = ps;
        T2[(ty * 8 + ii) * 16 + tx] = pq;
    }
    __syncthreads();

    if (tid < 128) {
        float s1 = 0.0f, s2 = 0.0f;
#pragma unroll
        for (int t = 0; t < 16; t++) { s1 += T1[tid * 16 + t]; s2 += T2[tid * 16 + t]; }
        float mu  = s1 * (1.0f / 128.0f);
        float var = s2 * (1.0f / 128.0f) - mu * mu;
        Ash[tid]       = mu;
        Ash[128 + tid] = rsqrtf(var + 1e-5f);
    }
    __syncthreads();

    float* obase = g_y + tok0 * DMODEL + hh * DHEAD;
    __nv_bfloat16* ohbase = g_y_h + tok0 * DMODEL + hh * DHEAD;
    __nv_bfloat16* olbase = g_y_l + tok0 * DMODEL + hh * DHEAD;
#pragma unroll
    for (int ii = 0; ii < 8; ii++) {
        int i = ty * 8 + ii;
        float mu = Ash[i], rs = Ash[128 + i];
        float o[8];
#pragma unroll
        for (int jj = 0; jj < 8; jj++) o[jj] = (vals[ii][jj] - mu) * rs;
        float* row = obase + (size_t)i * DMODEL + tx * 8;
        *(float4*)(row + 0) = make_float4(o[0], o[1], o[2], o[3]);
        *(float4*)(row + 4) = make_float4(o[4], o[5], o[6], o[7]);
        __nv_bfloat16 hv[8], lv[8];
#pragma unroll
        for (int jj = 0; jj < 8; jj++) split2(o[jj], hv[jj], lv[jj]);
        *(uint4*)(ohbase + (size_t)i * DMODEL + tx * 8) = *(uint4*)hv;
        *(uint4*)(olbase + (size_t)i * DMODEL + tx * 8) = *(uint4*)lv;
    }
}

// ================= host launcher =================
extern "C" void kernel_launch(void* const* d_in, const int* in_sizes, int n_in,
                              void* d_out, int out_size)
{
    (void)in_sizes; (void)n_in; (void)out_size;
    const float* x       = (const float*)d_in[0];
    const float* W_in    = (const float*)d_in[1];
    const float* W_embed = (const float*)d_in[2];
    const float* b_embed = (const float*)d_in[3];
    const float* W_out   = (const float*)d_in[4];
    float* out = (float*)d_out;

    float *qkv, *qe, *ke;
    __nv_bfloat16 *qkv_h, *qkv_l, *x_h, *x_l, *win_h, *win_l, *wemb_h, *wemb_l, *wout_h, *wout_l, *y_h, *y_l;
    cudaGetSymbolAddress((void**)&qkv,   g_qkv);
    cudaGetSymbolAddress((void**)&qe,    g_qe);
    cudaGetSymbolAddress((void**)&ke,    g_ke);
    cudaGetSymbolAddress((void**)&qkv_h, g_qkv_h);
    cudaGetSymbolAddress((void**)&qkv_l, g_qkv_l);
    cudaGetSymbolAddress((void**)&x_h,   g_x_h);
    cudaGetSymbolAddress((void**)&x_l,   g_x_l);
    cudaGetSymbolAddress((void**)&win_h, g_win_h);
    cudaGetSymbolAddress((void**)&win_l, g_win_l);
    cudaGetSymbolAddress((void**)&wemb_h,g_wemb_h);
    cudaGetSymbolAddress((void**)&wemb_l,g_wemb_l);
    cudaGetSymbolAddress((void**)&wout_h,g_wout_h);
    cudaGetSymbolAddress((void**)&wout_l,g_wout_l);
    cudaGetSymbolAddress((void**)&y_h,   g_y_h);
    cudaGetSymbolAddress((void**)&y_l,   g_y_l);
    float* y; cudaGetSymbolAddress((void**)&y, g_y);

    const int smem_k5 = (128 * APITCH + 2 * 16 * TP) * 4;
    cudaFuncSetAttribute(chunk_out_kernel, cudaFuncAttributeMaxDynamicSharedMemorySize, smem_k5);
    cudaFuncSetAttribute(gemm_tc_kernel, cudaFuncAttributeMaxDynamicSharedMemorySize, GEMM_SMEM);

    // splits
    {
        long long n4;
        n4 = (long long)NTOK * DMODEL / 4;
        split_kernel<<<(unsigned)((n4 + 255) / 256), 256>>>(x, x_h, x_l, n4);
        n4 = (long long)NQKV * DMODEL / 4;
        split_kernel<<<(unsigned)((n4 + 255) / 256), 256>>>(W_in, win_h, win_l, n4);
        n4 = (long long)DMODEL * DMODEL / 4;
        split_kernel<<<(unsigned)((n4 + 255) / 256), 256>>>(W_embed, wemb_h, wemb_l, n4);
        split_kernel<<<(unsigned)((n4 + 255) / 256), 256>>>(W_out, wout_h, wout_l, n4);
    }

    // 1) qkv = x @ W_in^T  (+ bf16 split output)
    gemm_tc_kernel<<<dim3(NQKV / 256, NTOK / 128), 256, GEMM_SMEM>>>(
        x_h, x_l, DMODEL, win_h, win_l, DMODEL,
        qkv, qkv_h, qkv_l, NQKV, DMODEL, nullptr, 1.0f);

    // 2) qe = qkv[:,0:2048] @ W_embed^T + b
    gemm_tc_kernel<<<dim3(DMODEL / 256, NTOK / 128), 256, GEMM_SMEM>>>(
        qkv_h, qkv_l, NQKV, wemb_h, wemb_l, DMODEL,
        qe, nullptr, nullptr, DMODEL, DMODEL, b_embed, 1.0f);

    // 3) ke = (qkv[:,2048:4096] @ W_embed^T + b) * QK_SCALE
    gemm_tc_kernel<<<dim3(DMODEL / 256, NTOK / 128), 256, GEMM_SMEM>>>(
        qkv_h + 2048, qkv_l + 2048, NQKV, wemb_h, wemb_l, DMODEL,
        ke, nullptr, nullptr, DMODEL, DMODEL, b_embed, QK_SCALE);

    // 4) per-chunk KV products
    chunk_kv_kernel<<<dim3(NCHUNK, NHEAD, BATCH), 256>>>();

    // 5) state scan
    scan_kernel<<<dim3(128 * 128 / 256, BATCH * NHEAD), 256>>>();

    // 6) per-chunk output + fused LayerNorm (+ bf16 split of y)
    chunk_out_kernel<<<dim3(NCHUNK, NHEAD, BATCH), 256, smem_k5>>>();

    // 7) out = y @ W_out^T
    gemm_tc_kernel<<<dim3(DMODEL / 256, NTOK / 128), 256, GEMM_SMEM>>>(
        y_h, y_l, DMODEL, wout_h, wout_l, DMODEL,
        out, nullptr, nullptr, DMODEL, DMODEL, nullptr, 1.0f);
}

// round 12
// speedup vs baseline: 2.6343x; 1.1567x over previous
#include <cuda_runtime.h>
#include <cuda_bf16.h>
#include <math.h>
#include <stdint.h>

// ---------------- problem constants ----------------
#define BATCH   2
#define SEQ     8192
#define NTOK    (BATCH*SEQ)        // 16384
#define DMODEL  2048
#define NQKV    6144
#define NHEAD   16
#define DHEAD   128
#define NCHUNK  64
#define CHUNKL  128
#define QK_SCALE 0.08838834764831845f

#define TP 132
#define APITCH 129

// tcgen05 is only legal on arch-specific / family-specific targets.
#if defined(__CUDA_ARCH__) && (defined(__CUDA_ARCH_FEAT_SM103_ALL) || defined(__CUDA_ARCH_FEAT_SM100_ALL) || defined(__CUDA_ARCH_FEAT_SM101_ALL) || defined(__CUDA_ARCH_FAMILY_SPECIFIC__) || defined(__CUDA_ARCH_SPECIFIC__))
#define HAS_TC 1
#else
#define HAS_TC 0
#endif

// ---------------- device scratch ----------------
__device__ float g_qkv[(size_t)NTOK * NQKV];
__device__ __nv_bfloat16 g_qkv_h[(size_t)NTOK * NQKV];
__device__ __nv_bfloat16 g_qkv_l[(size_t)NTOK * NQKV];
__device__ float g_qe [(size_t)NTOK * DMODEL];
__device__ float g_ke [(size_t)NTOK * DMODEL];
__device__ float g_st [(size_t)BATCH * NHEAD * NCHUNK * 128 * 128];
__device__ float g_y  [(size_t)NTOK * DMODEL];
__device__ __nv_bfloat16 g_y_h[(size_t)NTOK * DMODEL];
__device__ __nv_bfloat16 g_y_l[(size_t)NTOK * DMODEL];
__device__ __nv_bfloat16 g_x_h[(size_t)NTOK * DMODEL];
__device__ __nv_bfloat16 g_x_l[(size_t)NTOK * DMODEL];
__device__ __nv_bfloat16 g_win_h[(size_t)NQKV * DMODEL];
__device__ __nv_bfloat16 g_win_l[(size_t)NQKV * DMODEL];
__device__ __nv_bfloat16 g_wemb_h[(size_t)DMODEL * DMODEL];
__device__ __nv_bfloat16 g_wemb_l[(size_t)DMODEL * DMODEL];
__device__ __nv_bfloat16 g_wout_h[(size_t)DMODEL * DMODEL];
__device__ __nv_bfloat16 g_wout_l[(size_t)DMODEL * DMODEL];

__device__ __forceinline__ float head_slope(int h) {
    return -logf(1.0f - exp2f(-5.0f - (float)h));
}

__device__ __forceinline__ void split2(float v, __nv_bfloat16& h, __nv_bfloat16& l) {
    h = __float2bfloat16_rn(v);
    l = __float2bfloat16_rn(v - __bfloat162float(h));
}

// ================= PTX helpers =================
__device__ __forceinline__ uint32_t smem_to_u32(const void* p) {
    uint32_t a;
    asm("{ .reg .u64 t; cvta.to.shared.u64 t, %1; cvt.u32.u64 %0, t; }" : "=r"(a) : "l"(p));
    return a;
}
#define MBARRIER_INIT(mbar, count) \
    asm volatile("mbarrier.init.shared.b64 [%0], %1;" \
        :: "r"((uint32_t)(mbar)), "r"((uint32_t)(count)) : "memory")
#define MBARRIER_INVAL(mbar) \
    asm volatile("mbarrier.inval.shared.b64 [%0];" \
        :: "r"((uint32_t)(mbar)) : "memory")
#define MBARRIER_ARRIVE(mbar) \
    asm volatile("mbarrier.arrive.shared.b64 _, [%0];" \
        :: "r"((uint32_t)(mbar)) : "memory")
#define MBARRIER_WAIT_PARITY(mbar_smem_addr, phase_parity) do { \
    uint32_t _mbar = (uint32_t)(mbar_smem_addr); \
    uint32_t _parity = (uint32_t)(phase_parity); \
    uint32_t _done; \
    asm volatile( \
        "{\n\t.reg .pred p;\n\t" \
        "mbarrier.try_wait.parity.acquire.cta.shared::cta.b64 p, [%1], %2;\n\t" \
        "selp.b32 %0, 1, 0, p;\n\t}" \
        : "=r"(_done) : "r"(_mbar), "r"(_parity) : "memory"); \
    if (!_done) { \
        asm volatile( \
            "{\n\t.reg .pred P1;\n\t" \
            "WAIT_LOOP_%=:\n\t" \
            "mbarrier.try_wait.parity.acquire.cta.shared::cta.b64 P1, [%0], %1, 0x989680;\n\t" \
            "@P1 bra.uni WAIT_DONE_%=;\n\t" \
            "bra.uni WAIT_LOOP_%=;\n\t" \
            "WAIT_DONE_%=:\n\t}" \
            :: "r"(_mbar), "r"(_parity) : "memory"); \
    } \
} while(0)
#define FENCE_PROXY_ASYNC_SHARED_CTA() \
    asm volatile("fence.proxy.async.shared::cta;" ::: "memory")

#if HAS_TC
__device__ __forceinline__ uint32_t elect_one_pred() {
    uint32_t pred;
    asm volatile(
        "{\n\t.reg .pred p;\n\t"
        "elect.sync _|p, 0xFFFFFFFF;\n\t"
        "selp.b32 %0, 1, 0, p;\n\t}"
        : "=r"(pred));
    return pred;
}
#define TCGEN05_ALLOC(smem_result_addr, nCols) \
    asm volatile("tcgen05.alloc.cta_group::1.sync.aligned.shared::cta.b32 [%0], %1;" \
        :: "r"((uint32_t)(smem_result_addr)), "r"((uint32_t)(nCols)) : "memory")
#define TCGEN05_DEALLOC(tmem_addr, nCols) \
    asm volatile("tcgen05.dealloc.cta_group::1.sync.aligned.b32 %0, %1;" \
        :: "r"(tmem_addr), "r"((uint32_t)(nCols)))
#define TCGEN05_COMMIT(mbar) \
    asm volatile("tcgen05.commit.cta_group::1.mbarrier::arrive::one.shared::cluster.b64 [%0];" \
        :: "r"((uint32_t)(mbar)) : "memory")
#define TCGEN05_FENCE_AFTER() \
    asm volatile("tcgen05.fence::after_thread_sync;" ::: "memory")
#define TCGEN05_FENCE_BEFORE() \
    asm volatile("tcgen05.fence::before_thread_sync;" ::: "memory")
#define TCGEN05_WAIT_LD() \
    asm volatile("tcgen05.wait::ld.sync.aligned;" ::: "memory")
#define TCGEN05_LD_32X32B_X32(r, tmem_addr) \
    asm volatile( \
        "tcgen05.ld.sync.aligned.32x32b.x32.b32 " \
        "{%0, %1, %2, %3, %4, %5, %6, %7, " \
        " %8, %9, %10, %11, %12, %13, %14, %15, " \
        " %16, %17, %18, %19, %20, %21, %22, %23, " \
        " %24, %25, %26, %27, %28, %29, %30, %31}, [%32];" \
        : "=r"((r)[0]),  "=r"((r)[1]),  "=r"((r)[2]),  "=r"((r)[3]), \
          "=r"((r)[4]),  "=r"((r)[5]),  "=r"((r)[6]),  "=r"((r)[7]), \
          "=r"((r)[8]),  "=r"((r)[9]),  "=r"((r)[10]), "=r"((r)[11]), \
          "=r"((r)[12]), "=r"((r)[13]), "=r"((r)[14]), "=r"((r)[15]), \
          "=r"((r)[16]), "=r"((r)[17]), "=r"((r)[18]), "=r"((r)[19]), \
          "=r"((r)[20]), "=r"((r)[21]), "=r"((r)[22]), "=r"((r)[23]), \
          "=r"((r)[24]), "=r"((r)[25]), "=r"((r)[26]), "=r"((r)[27]), \
          "=r"((r)[28]), "=r"((r)[29]), "=r"((r)[30]), "=r"((r)[31]) \
        : "r"(tmem_addr))

static constexpr uint64_t SMEM_DESC_BASE_SW128 =
    (uint64_t(2)  << 61) | (uint64_t(1) << 46) | (uint64_t(64) << 32) | (uint64_t(1) << 16);
#define MAKE_SMEM_DESC(base_addr) \
    (SMEM_DESC_BASE_SW128 | ((uint64_t)((base_addr) >> 4) & 0x3FFF))

// idesc: dtype=F32, atype=BF16, btype=BF16, K-major/K-major, M=128, N=64
#define IDESC_M128N64 ((1u<<4)|(1u<<7)|(1u<<10)|((64u/8u)<<17)|((128u/16u)<<24))

__device__ __forceinline__ void mma_f16_ss(uint32_t d_tmem, uint64_t a_desc,
                                           uint64_t b_desc, uint32_t idesc, bool acc) {
    uint32_t en = acc ? 1u : 0u;
    asm volatile(
        "{\n\t.reg .pred p;\n\t"
        "setp.ne.u32 p, %5, 0;\n\t"
        "tcgen05.mma.cta_group::1.kind::f16 [%0], %1, %2, %3, {%4, %4, %4, %4}, p;\n\t}"
        :: "r"(d_tmem), "l"(a_desc), "l"(b_desc), "r"(idesc), "r"(0u), "r"(en)
        : "memory");
}
#endif // HAS_TC

#define SWZ128(off) ((off) ^ (((off) >> 3) & 0x70))

// ================= fp32 -> (hi,lo) bf16 split =================
__global__ __launch_bounds__(256)
void split_kernel(const float* __restrict__ in, __nv_bfloat16* __restrict__ hi,
                  __nv_bfloat16* __restrict__ lo, long long n4)
{
    long long i = (long long)blockIdx.x * 256 + threadIdx.x;
    if (i >= n4) return;
    float4 v = ((const float4*)in)[i];
    __nv_bfloat16 h0,h1,h2,h3,l0,l1,l2,l3;
    split2(v.x,h0,l0); split2(v.y,h1,l1); split2(v.z,h2,l2); split2(v.w,h3,l3);
    __nv_bfloat162* hp = (__nv_bfloat162*)(hi + 4*i);
    __nv_bfloat162* lp = (__nv_bfloat162*)(lo + 4*i);
    hp[0] = __nv_bfloat162(h0,h1); hp[1] = __nv_bfloat162(h2,h3);
    lp[0] = __nv_bfloat162(l0,l1); lp[1] = __nv_bfloat162(l2,l3);
}

// ================= GEMM: tcgen05 bf16x3, warp-specialized producer/consumer ======
// C[m,n] = scale*(sum_k A[m,k]*B[n,k] + bias[n]); tile 128(M) x 256(N), KT=64.
// Warp 0: MMA issue only. Warps 1-7 (224 threads): loads. mbarrier handshake.
#define KT 64
#define STAGE_BYTES 98304
#define SMEM_TILE0 1024
#define GEMM_SMEM (SMEM_TILE0 + 2*STAGE_BYTES)   // 197632
// mbar layout: full0 @ sb+8, full1 @ sb+16, done0 @ sb+24, done1 @ sb+32

__global__ __launch_bounds__(256) __cluster_dims__(1, 1, 1)
void gemm_tc_kernel(const __nv_bfloat16* __restrict__ Ah, const __nv_bfloat16* __restrict__ Al, int lda,
                    const __nv_bfloat16* __restrict__ Bh, const __nv_bfloat16* __restrict__ Bl, int ldb,
                    float* __restrict__ C, __nv_bfloat16* __restrict__ Ch, __nv_bfloat16* __restrict__ Cl,
                    int ldc, int K, const float* __restrict__ bias, float scale)
{
    extern __shared__ __align__(1024) char smem[];
    const int tid = threadIdx.x;
    const int n0 = blockIdx.x * 256;
    const int m0 = blockIdx.y * 128;

#if HAS_TC
    const uint32_t sb = smem_to_u32(smem);
    const int wid = tid >> 5, lid = tid & 31;

    // warp 0 allocates TMEM; nobody relinquishes (avoids relinquish-before-alloc race)
    if (wid == 0) { TCGEN05_ALLOC(sb + 0, 256); }
    if (tid == 0) {
        MBARRIER_INIT(sb + 8,  224);   // full0: all loader threads arrive
        MBARRIER_INIT(sb + 16, 224);   // full1
        MBARRIER_INIT(sb + 24, 1);     // done0: tcgen05.commit
        MBARRIER_INIT(sb + 32, 1);     // done1
    }
    __syncthreads();
    uint32_t tmem;
    asm volatile("ld.shared.b32 %0, [%1];" : "=r"(tmem) : "r"(sb));

    const int ktiles = K / KT;

    if (tid >= 32) {
        // ---------------- loader warps (224 threads) ----------------
        const int lt = tid - 32;
        for (int t = 0; t < ktiles; t++) {
            const int buf = t & 1;
            if (t >= 2) {
                MBARRIER_WAIT_PARITY(sb + 24 + buf * 8, ((t - 2) >> 1) & 1);
            }
            char* st = smem + SMEM_TILE0 + buf * STAGE_BYTES;
            const int k0 = t * KT;
            // A hi/lo: 1024 uint4 each
            for (int i = lt; i < 1024; i += 224) {
                int row = i >> 3, c = i & 7;
                uint32_t sw = SWZ128((uint32_t)(row * 128 + c * 16));
                *(uint4*)(st + sw)         = *(const uint4*)(Ah + (size_t)(m0 + row) * lda + k0 + c * 8);
                *(uint4*)(st + 16384 + sw) = *(const uint4*)(Al + (size_t)(m0 + row) * lda + k0 + c * 8);
            }
            // B hi/lo: 2048 uint4 each
            for (int i = lt; i < 2048; i += 224) {
                int row = i >> 3, c = i & 7;
                uint32_t sw = SWZ128((uint32_t)(row * 128 + c * 16));
                *(uint4*)(st + 32768 + sw) = *(const uint4*)(Bh + (size_t)(n0 + row) * ldb + k0 + c * 8);
                *(uint4*)(st + 65536 + sw) = *(const uint4*)(Bl + (size_t)(n0 + row) * ldb + k0 + c * 8);
            }
            FENCE_PROXY_ASYNC_SHARED_CTA();
            MBARRIER_ARRIVE(sb + 8 + buf * 8);
        }
    } else if (elect_one_pred()) {
        // ---------------- MMA warp (single elected thread) ----------------
        for (int t = 0; t < ktiles; t++) {
            const int buf = t & 1;
            MBARRIER_WAIT_PARITY(sb + 8 + buf * 8, (t >> 1) & 1);
            uint32_t sbase = sb + SMEM_TILE0 + buf * STAGE_BYTES;
            uint64_t dAh = MAKE_SMEM_DESC(sbase);
            uint64_t dAl = MAKE_SMEM_DESC(sbase + 16384);
            uint64_t dBh = MAKE_SMEM_DESC(sbase + 32768);
            uint64_t dBl = MAKE_SMEM_DESC(sbase + 65536);
#pragma unroll
            for (int ks = 0; ks < 4; ks++) {
                uint64_t oa = ks * 2;           // +32B per K-step (16B units)
#pragma unroll
                for (int p = 0; p < 3; p++) {
                    uint64_t da = (p == 2) ? dAl : dAh;
                    uint64_t db = (p == 1) ? dBl : dBh;
                    bool first = (t == 0 && ks == 0 && p == 0);
#pragma unroll
                    for (int nq = 0; nq < 4; nq++) {
                        uint32_t d = tmem + nq * 64;          // 64 fp32 cols per N-quarter
                        uint64_t ob = oa + nq * 512;          // +64 rows*128B = 512 units
                        mma_f16_ss(d, da + oa, db + ob, IDESC_M128N64, !first);
                    }
                }
            }
            TCGEN05_COMMIT(sb + 24 + buf * 8);
        }
    }

    // all threads: wait for the final commits on both buffers
    {
        uint32_t ph = (((uint32_t)ktiles >> 1) - 1) & 1;
        MBARRIER_WAIT_PARITY(sb + 24, ph);
        MBARRIER_WAIT_PARITY(sb + 32, ph);
    }
    TCGEN05_FENCE_AFTER();
    __syncthreads();

    // epilogue: warp w: rows m0 + (w&3)*32 .. +31, cols (w>>2)*128 .. +127
    const int row = m0 + (wid & 3) * 32 + lid;
    const int colbase = (wid >> 2) * 128;
#pragma unroll
    for (int cq = 0; cq < 4; cq++) {
        const int cb = colbase + cq * 32;
        uint32_t regs[32];
        TCGEN05_LD_32X32B_X32(regs, tmem + cb);
        TCGEN05_WAIT_LD();
        float v[32];
#pragma unroll
        for (int c = 0; c < 32; c++) {
            float bv = bias ? bias[n0 + cb + c] : 0.0f;
            v[c] = scale * (__uint_as_float(regs[c]) + bv);
        }
        float* crow = C + (size_t)row * ldc + n0 + cb;
#pragma unroll
        for (int c4 = 0; c4 < 8; c4++) {
            *(float4*)(crow + c4 * 4) = make_float4(v[c4*4], v[c4*4+1], v[c4*4+2], v[c4*4+3]);
        }
        if (Ch) {
            __nv_bfloat16 hv[32], lv[32];
#pragma unroll
            for (int c = 0; c < 32; c++) split2(v[c], hv[c], lv[c]);
            __nv_bfloat16* hrow = Ch + (size_t)row * ldc + n0 + cb;
            __nv_bfloat16* lrow = Cl + (size_t)row * ldc + n0 + cb;
#pragma unroll
            for (int c8 = 0; c8 < 4; c8++) {
                *(uint4*)(hrow + c8 * 8) = *(uint4*)&hv[c8 * 8];
                *(uint4*)(lrow + c8 * 8) = *(uint4*)&lv[c8 * 8];
            }
        }
    }
    TCGEN05_FENCE_BEFORE();
    __syncthreads();
    if (tid == 0) {
        MBARRIER_INVAL(sb + 8);  MBARRIER_INVAL(sb + 16);
        MBARRIER_INVAL(sb + 24); MBARRIER_INVAL(sb + 32);
    }
    __syncthreads();
    if (wid == 0) { TCGEN05_DEALLOC(tmem, 256); }

#else  // ---------------- FMA fallback (256 threads; correctness-only path) ----------------
    (void)smem;
    const int tx = tid & 15, ty = tid >> 4;   // 16 x 16

    for (int half = 0; half < 2; half++) {
        const int nbase = n0 + half * 128;
        float acc[8][8];
#pragma unroll
        for (int i = 0; i < 8; i++)
#pragma unroll
            for (int j = 0; j < 8; j++) acc[i][j] = 0.0f;

        for (int k0 = 0; k0 < K; k0 += 16) {
#pragma unroll
            for (int kk = 0; kk < 16; kk++) {
                float a[8], b[8];
#pragma unroll
                for (int u = 0; u < 8; u++) {
                    size_t ia = (size_t)(m0 + ty * 8 + u) * lda + k0 + kk;
                    a[u] = __bfloat162float(Ah[ia]) + __bfloat162float(Al[ia]);
                }
#pragma unroll
                for (int u = 0; u < 8; u++) {
                    size_t ib = (size_t)(nbase + tx * 8 + u) * ldb + k0 + kk;
                    b[u] = __bfloat162float(Bh[ib]) + __bfloat162float(Bl[ib]);
                }
#pragma unroll
                for (int i = 0; i < 8; i++)
#pragma unroll
                    for (int j = 0; j < 8; j++)
                        acc[i][j] = fmaf(a[i], b[j], acc[i][j]);
            }
        }

        float bv[8];
#pragma unroll
        for (int j = 0; j < 8; j++) bv[j] = bias ? bias[nbase + tx * 8 + j] : 0.0f;
#pragma unroll
        for (int i = 0; i < 8; i++) {
            int r = m0 + ty * 8 + i;
            float v[8];
#pragma unroll
            for (int j = 0; j < 8; j++) v[j] = scale * (acc[i][j] + bv[j]);
            float* crow = C + (size_t)r * ldc + nbase + tx * 8;
            *(float4*)(crow + 0) = make_float4(v[0], v[1], v[2], v[3]);
            *(float4*)(crow + 4) = make_float4(v[4], v[5], v[6], v[7]);
            if (Ch) {
                __nv_bfloat16 hv[8], lv[8];
#pragma unroll
                for (int j = 0; j < 8; j++) split2(v[j], hv[j], lv[j]);
                *(uint4*)(Ch + (size_t)r * ldc + nbase + tx * 8) = *(uint4*)hv;
                *(uint4*)(Cl + (size_t)r * ldc + nbase + tx * 8) = *(uint4*)lv;
            }
        }
    }
#endif
}

// ================= attention kernels =================
__global__ __launch_bounds__(256)
void chunk_kv_kernel()
{
    __shared__ float Ks[16][TP];
    __shared__ float Vs[16][TP];
    const int c = blockIdx.x, h = blockIdx.y, b = blockIdx.z;
    const int tid = threadIdx.x;
    const int tx = tid & 15, ty = tid >> 4;
    const float s = head_slope(h);

    const float* kbase = g_ke  + ((size_t)(b * SEQ + c * CHUNKL)) * DMODEL + h * DHEAD;
    const float* vbase = g_qkv + ((size_t)(b * SEQ + c * CHUNKL)) * NQKV  + 4096 + h * DHEAD;

    float acc[8][8];
#pragma unroll
    for (int i = 0; i < 8; i++)
#pragma unroll
        for (int j = 0; j < 8; j++) acc[i][j] = 0.0f;

    for (int j0 = 0; j0 < CHUNKL; j0 += 16) {
#pragma unroll
        for (int it = 0; it < 2; it++) {
            int f   = tid + it * 256;
            int row = f >> 5;
            int c4  = (f & 31) * 4;
            int j   = j0 + row;
            float kd = expf(-s * (float)(CHUNKL - 1 - j));
            float4 kv = *(const float4*)(kbase + (size_t)j * DMODEL + c4);
            kv.x *= kd; kv.y *= kd; kv.z *= kd; kv.w *= kd;
            *(float4*)&Ks[row][c4] = kv;
            float4 vv = *(const float4*)(vbase + (size_t)j * NQKV + c4);
            *(float4*)&Vs[row][c4] = vv;
        }
        __syncthreads();
#pragma unroll
        for (int kk = 0; kk < 16; kk++) {
            float a[8], bb[8];
#pragma unroll
            for (int u = 0; u < 8; u++) a[u]  = Ks[kk][ty * 8 + u];
#pragma unroll
            for (int u = 0; u < 8; u++) bb[u] = Vs[kk][tx * 8 + u];
#pragma unroll
            for (int i = 0; i < 8; i++)
#pragma unroll
                for (int j = 0; j < 8; j++)
                    acc[i][j] = fmaf(a[i], bb[j], acc[i][j]);
        }
        __syncthreads();
    }

    float* gout = g_st + ((size_t)((b * NHEAD + h) * NCHUNK + c)) * (128 * 128);
#pragma unroll
    for (int i = 0; i < 8; i++) {
        float* row = gout + (size_t)(ty * 8 + i) * 128 + tx * 8;
        *(float4*)(row + 0) = make_float4(acc[i][0], acc[i][1], acc[i][2], acc[i][3]);
        *(float4*)(row + 4) = make_float4(acc[i][4], acc[i][5], acc[i][6], acc[i][7]);
    }
}

__global__ __launch_bounds__(256)
void scan_kernel()
{
    const int bh = blockIdx.y;
    const int h  = bh & (NHEAD - 1);
    const float s   = head_slope(h);
    const float lam = expf(-s * (float)CHUNKL);
    const int e = blockIdx.x * 256 + threadIdx.x;
    float* base = g_st + (size_t)bh * NCHUNK * (128 * 128) + e;
    float S = 0.0f;
#pragma unroll 4
    for (int c = 0; c < NCHUNK; c++) {
        float g = base[(size_t)c * (128 * 128)];
        base[(size_t)c * (128 * 128)] = S;
        S = fmaf(lam, S, g);
    }
}

__global__ __launch_bounds__(256)
void chunk_out_kernel()
{
    extern __shared__ float sm[];
    float* Ash = sm;
    float* T1  = sm + 128 * APITCH;
    float* T2  = T1 + 16 * TP;

    const int c = blockIdx.x, hh = blockIdx.y, b = blockIdx.z;
    const int tid = threadIdx.x;
    const int tx = tid & 15, ty = tid >> 4;
    const float s = head_slope(hh);

    const size_t tok0 = (size_t)(b * SEQ + c * CHUNKL);
    const float* qbase = g_qe  + tok0 * DMODEL + hh * DHEAD;
    const float* kbase = g_ke  + tok0 * DMODEL + hh * DHEAD;
    const float* vbase = g_qkv + tok0 * NQKV  + 4096 + hh * DHEAD;
    const float* Sbase = g_st  + ((size_t)((b * NHEAD + hh) * NCHUNK + c)) * (128 * 128);

    float acc[8][8];
#pragma unroll
    for (int i = 0; i < 8; i++)
#pragma unroll
        for (int j = 0; j < 8; j++) acc[i][j] = 0.0f;

    for (int d0 = 0; d0 < DHEAD; d0 += 16) {
#pragma unroll
        for (int it = 0; it < 2; it++) {
            int f   = tid + it * 256;
            int row = f >> 2;
            int kq  = (f & 3) * 4;
            float4 qv = *(const float4*)(qbase + (size_t)row * DMODEL + d0 + kq);
            T1[(kq + 0) * TP + row] = qv.x; T1[(kq + 1) * TP + row] = qv.y;
            T1[(kq + 2) * TP + row] = qv.z; T1[(kq + 3) * TP + row] = qv.w;
            float4 kv = *(const float4*)(kbase + (size_t)row * DMODEL + d0 + kq);
            T2[(kq + 0) * TP + row] = kv.x; T2[(kq + 1) * TP + row] = kv.y;
            T2[(kq + 2) * TP + row] = kv.z; T2[(kq + 3) * TP + row] = kv.w;
        }
        __syncthreads();
#pragma unroll
        for (int kk = 0; kk < 16; kk++) {
            float a[8], bb[8];
#pragma unroll
            for (int u = 0; u < 8; u++) a[u]  = T1[kk * TP + ty * 8 + u];
#pragma unroll
            for (int u = 0; u < 8; u++) bb[u] = T2[kk * TP + tx * 8 + u];
#pragma unroll
            for (int i = 0; i < 8; i++)
#pragma unroll
                for (int j = 0; j < 8; j++)
                    acc[i][j] = fmaf(a[i], bb[j], acc[i][j]);
        }
        __syncthreads();
    }

#pragma unroll
    for (int jj = 0; jj < 8; jj++) {
#pragma unroll
        for (int ii = 0; ii < 8; ii++) {
            int i = ty * 8 + ii, j = tx * 8 + jj;
            float v = (i >= j) ? acc[ii][jj] * expf(-s * (float)(i - j)) : 0.0f;
            Ash[j * APITCH + i] = v;
        }
    }
    __syncthreads();

    float accO[8][8];
#pragma unroll
    for (int i = 0; i < 8; i++)
#pragma unroll
        for (int j = 0; j < 8; j++) accO[i][j] = 0.0f;

    for (int j0 = 0; j0 < CHUNKL; j0 += 16) {
#pragma unroll
        for (int it = 0; it < 2; it++) {
            int f   = tid + it * 256;
            int row = f >> 5;
            int c4  = (f & 31) * 4;
            float4 vv = *(const float4*)(vbase + (size_t)(j0 + row) * NQKV + c4);
            *(float4*)&T1[row * TP + c4] = vv;
        }
        __syncthreads();
#pragma unroll
        for (int kk = 0; kk < 16; kk++) {
            float a[8], bb[8];
#pragma unroll
            for (int u = 0; u < 8; u++) a[u]  = Ash[(j0 + kk) * APITCH + ty * 8 + u];
#pragma unroll
            for (int u = 0; u < 8; u++) bb[u] = T1[kk * TP + tx * 8 + u];
#pragma unroll
            for (int i = 0; i < 8; i++)
#pragma unroll
                for (int j = 0; j < 8; j++)
                    accO[i][j] = fmaf(a[i], bb[j], accO[i][j]);
        }
        __syncthreads();
    }

    float acc2[8][8];
#pragma unroll
    for (int i = 0; i < 8; i++)
#pragma unroll
        for (int j = 0; j < 8; j++) acc2[i][j] = 0.0f;

    for (int d0 = 0; d0 < DHEAD; d0 += 16) {
#pragma unroll
        for (int it = 0; it < 2; it++) {
            int f   = tid + it * 256;
            int row = f >> 2;
            int kq  = (f & 3) * 4;
            float4 qv = *(const float4*)(qbase + (size_t)row * DMODEL + d0 + kq);
            T1[(kq + 0) * TP + row] = qv.x; T1[(kq + 1) * TP + row] = qv.y;
            T1[(kq + 2) * TP + row] = qv.z; T1[(kq + 3) * TP + row] = qv.w;
        }
#pragma unroll
        for (int it = 0; it < 2; it++) {
            int f   = tid + it * 256;
            int row = f >> 5;
            int c4  = (f & 31) * 4;
            float4 sv = *(const float4*)(Sbase + (size_t)(d0 + row) * 128 + c4);
            *(float4*)&T2[row * TP + c4] = sv;
        }
        __syncthreads();
#pragma unroll
        for (int kk = 0; kk < 16; kk++) {
            float a[8], bb[8];
#pragma unroll
            for (int u = 0; u < 8; u++) a[u]  = T1[kk * TP + ty * 8 + u];
#pragma unroll
            for (int u = 0; u < 8; u++) bb[u] = T2[kk * TP + tx * 8 + u];
#pragma unroll
            for (int i = 0; i < 8; i++)
#pragma unroll
                for (int j = 0; j < 8; j++)
                    acc2[i][j] = fmaf(a[i], bb[j], acc2[i][j]);
        }
        __syncthreads();
    }

    float vals[8][8];
#pragma unroll
    for (int ii = 0; ii < 8; ii++) {
        float qd = expf(-s * (float)(ty * 8 + ii + 1));
#pragma unroll
        for (int jj = 0; jj < 8; jj++)
            vals[ii][jj] = accO[ii][jj] + qd * acc2[ii][jj];
    }

#pragma unroll
    for (int ii = 0; ii < 8; ii++) {
        float ps = 0.0f, pq = 0.0f;
#pragma unroll
        for (int jj = 0; jj < 8; jj++) { float v = vals[ii][jj]; ps += v; pq += v * v; }
        T1[(ty * 8 + ii) * 16 + tx] = ps;
        T2[(ty * 8 + ii) * 16 + tx] = pq;
    }
    __syncthreads();

    if (tid < 128) {
        float s1 = 0.0f, s2 = 0.0f;
#pragma unroll
        for (int t = 0; t < 16; t++) { s1 += T1[tid * 16 + t]; s2 += T2[tid * 16 + t]; }
        float mu  = s1 * (1.0f / 128.0f);
        float var = s2 * (1.0f / 128.0f) - mu * mu;
        Ash[tid]       = mu;
        Ash[128 + tid] = rsqrtf(var + 1e-5f);
    }
    __syncthreads();

    float* obase = g_y + tok0 * DMODEL + hh * DHEAD;
    __nv_bfloat16* ohbase = g_y_h + tok0 * DMODEL + hh * DHEAD;
    __nv_bfloat16* olbase = g_y_l + tok0 * DMODEL + hh * DHEAD;
#pragma unroll
    for (int ii = 0; ii < 8; ii++) {
        int i = ty * 8 + ii;
        float mu = Ash[i], rs = Ash[128 + i];
        float o[8];
#pragma unroll
        for (int jj = 0; jj < 8; jj++) o[jj] = (vals[ii][jj] - mu) * rs;
        float* row = obase + (size_t)i * DMODEL + tx * 8;
        *(float4*)(row + 0) = make_float4(o[0], o[1], o[2], o[3]);
        *(float4*)(row + 4) = make_float4(o[4], o[5], o[6], o[7]);
        __nv_bfloat16 hv[8], lv[8];
#pragma unroll
        for (int jj = 0; jj < 8; jj++) split2(o[jj], hv[jj], lv[jj]);
        *(uint4*)(ohbase + (size_t)i * DMODEL + tx * 8) = *(uint4*)hv;
        *(uint4*)(olbase + (size_t)i * DMODEL + tx * 8) = *(uint4*)lv;
    }
}

// ================= host launcher =================
extern "C" void kernel_launch(void* const* d_in, const int* in_sizes, int n_in,
                              void* d_out, int out_size)
{
    (void)in_sizes; (void)n_in; (void)out_size;
    const float* x       = (const float*)d_in[0];
    const float* W_in    = (const float*)d_in[1];
    const float* W_embed = (const float*)d_in[2];
    const float* b_embed = (const float*)d_in[3];
    const float* W_out   = (const float*)d_in[4];
    float* out = (float*)d_out;

    float *qkv, *qe, *ke;
    __nv_bfloat16 *qkv_h, *qkv_l, *x_h, *x_l, *win_h, *win_l, *wemb_h, *wemb_l, *wout_h, *wout_l, *y_h, *y_l;
    cudaGetSymbolAddress((void**)&qkv,   g_qkv);
    cudaGetSymbolAddress((void**)&qe,    g_qe);
    cudaGetSymbolAddress((void**)&ke,    g_ke);
    cudaGetSymbolAddress((void**)&qkv_h, g_qkv_h);
    cudaGetSymbolAddress((void**)&qkv_l, g_qkv_l);
    cudaGetSymbolAddress((void**)&x_h,   g_x_h);
    cudaGetSymbolAddress((void**)&x_l,   g_x_l);
    cudaGetSymbolAddress((void**)&win_h, g_win_h);
    cudaGetSymbolAddress((void**)&win_l, g_win_l);
    cudaGetSymbolAddress((void**)&wemb_h,g_wemb_h);
    cudaGetSymbolAddress((void**)&wemb_l,g_wemb_l);
    cudaGetSymbolAddress((void**)&wout_h,g_wout_h);
    cudaGetSymbolAddress((void**)&wout_l,g_wout_l);
    cudaGetSymbolAddress((void**)&y_h,   g_y_h);
    cudaGetSymbolAddress((void**)&y_l,   g_y_l);
    float* y; cudaGetSymbolAddress((void**)&y, g_y);

    const int smem_k5 = (128 * APITCH + 2 * 16 * TP) * 4;
    cudaFuncSetAttribute(chunk_out_kernel, cudaFuncAttributeMaxDynamicSharedMemorySize, smem_k5);
    cudaFuncSetAttribute(gemm_tc_kernel, cudaFuncAttributeMaxDynamicSharedMemorySize, GEMM_SMEM);

    // splits
    {
        long long n4;
        n4 = (long long)NTOK * DMODEL / 4;
        split_kernel<<<(unsigned)((n4 + 255) / 256), 256>>>(x, x_h, x_l, n4);
        n4 = (long long)NQKV * DMODEL / 4;
        split_kernel<<<(unsigned)((n4 + 255) / 256), 256>>>(W_in, win_h, win_l, n4);
        n4 = (long long)DMODEL * DMODEL / 4;
        split_kernel<<<(unsigned)((n4 + 255) / 256), 256>>>(W_embed, wemb_h, wemb_l, n4);
        split_kernel<<<(unsigned)((n4 + 255) / 256), 256>>>(W_out, wout_h, wout_l, n4);
    }

    // 1) qkv = x @ W_in^T  (+ bf16 split output)
    gemm_tc_kernel<<<dim3(NQKV / 256, NTOK / 128), 256, GEMM_SMEM>>>(
        x_h, x_l, DMODEL, win_h, win_l, DMODEL,
        qkv, qkv_h, qkv_l, NQKV, DMODEL, nullptr, 1.0f);

    // 2) qe = qkv[:,0:2048] @ W_embed^T + b
    gemm_tc_kernel<<<dim3(DMODEL / 256, NTOK / 128), 256, GEMM_SMEM>>>(
        qkv_h, qkv_l, NQKV, wemb_h, wemb_l, DMODEL,
        qe, nullptr, nullptr, DMODEL, DMODEL, b_embed, 1.0f);

    // 3) ke = (qkv[:,2048:4096] @ W_embed^T + b) * QK_SCALE
    gemm_tc_kernel<<<dim3(DMODEL / 256, NTOK / 128), 256, GEMM_SMEM>>>(
        qkv_h + 2048, qkv_l + 2048, NQKV, wemb_h, wemb_l, DMODEL,
        ke, nullptr, nullptr, DMODEL, DMODEL, b_embed, QK_SCALE);

    // 4) per-chunk KV products
    chunk_kv_kernel<<<dim3(NCHUNK, NHEAD, BATCH), 256>>>();

    // 5) state scan
    scan_kernel<<<dim3(128 * 128 / 256, BATCH * NHEAD), 256>>>();

    // 6) per-chunk output + fused LayerNorm (+ bf16 split of y)
    chunk_out_kernel<<<dim3(NCHUNK, NHEAD, BATCH), 256, smem_k5>>>();

    // 7) out = y @ W_out^T
    gemm_tc_kernel<<<dim3(DMODEL / 256, NTOK / 128), 256, GEMM_SMEM>>>(
        y_h, y_l, DMODEL, wout_h, wout_l, DMODEL,
        out, nullptr, nullptr, DMODEL, DMODEL, nullptr, 1.0f);
}

// round 14
// speedup vs baseline: 3.9698x; 1.5070x over previous
#include <cuda_runtime.h>
#include <cuda_bf16.h>
#include <math.h>
#include <stdint.h>

// ---------------- problem constants ----------------
#define BATCH   2
#define SEQ     8192
#define NTOK    (BATCH*SEQ)        // 16384
#define DMODEL  2048
#define NQKV    6144
#define NHEAD   16
#define DHEAD   128
#define NCHUNK  64
#define CHUNKL  128
#define QK_SCALE 0.08838834764831845f

#define TP 132
#define APITCH 129

// tcgen05 is only legal on arch-specific / family-specific targets.
#if defined(__CUDA_ARCH__) && (defined(__CUDA_ARCH_FEAT_SM103_ALL) || defined(__CUDA_ARCH_FEAT_SM100_ALL) || defined(__CUDA_ARCH_FEAT_SM101_ALL) || defined(__CUDA_ARCH_FAMILY_SPECIFIC__) || defined(__CUDA_ARCH_SPECIFIC__))
#define HAS_TC 1
#else
#define HAS_TC 0
#endif

// ---------------- device scratch ----------------
__device__ __nv_bfloat16 g_qkv_h[(size_t)NTOK * NQKV];
__device__ __nv_bfloat16 g_qkv_l[(size_t)NTOK * NQKV];
__device__ float g_qe [(size_t)NTOK * DMODEL];
__device__ float g_ke [(size_t)NTOK * DMODEL];
__device__ float g_st [(size_t)BATCH * NHEAD * NCHUNK * 128 * 128];
__device__ float g_y  [(size_t)NTOK * DMODEL];
__device__ __nv_bfloat16 g_y_h[(size_t)NTOK * DMODEL];
__device__ __nv_bfloat16 g_y_l[(size_t)NTOK * DMODEL];
__device__ __nv_bfloat16 g_x_h[(size_t)NTOK * DMODEL];
__device__ __nv_bfloat16 g_x_l[(size_t)NTOK * DMODEL];
__device__ __nv_bfloat16 g_win_h[(size_t)NQKV * DMODEL];
__device__ __nv_bfloat16 g_win_l[(size_t)NQKV * DMODEL];
__device__ __nv_bfloat16 g_wemb_h[(size_t)DMODEL * DMODEL];
__device__ __nv_bfloat16 g_wemb_l[(size_t)DMODEL * DMODEL];
__device__ __nv_bfloat16 g_wout_h[(size_t)DMODEL * DMODEL];
__device__ __nv_bfloat16 g_wout_l[(size_t)DMODEL * DMODEL];

__device__ __forceinline__ float head_slope(int h) {
    return -logf(1.0f - exp2f(-5.0f - (float)h));
}

__device__ __forceinline__ void split2(float v, __nv_bfloat16& h, __nv_bfloat16& l) {
    h = __float2bfloat16_rn(v);
    l = __float2bfloat16_rn(v - __bfloat162float(h));
}

// ================= PTX helpers =================
__device__ __forceinline__ uint32_t smem_to_u32(const void* p) {
    uint32_t a;
    asm("{ .reg .u64 t; cvta.to.shared.u64 t, %1; cvt.u32.u64 %0, t; }" : "=r"(a) : "l"(p));
    return a;
}
#define MBARRIER_INIT(mbar, count) \
    asm volatile("mbarrier.init.shared.b64 [%0], %1;" \
        :: "r"((uint32_t)(mbar)), "r"((uint32_t)(count)) : "memory")
#define MBARRIER_INVAL(mbar) \
    asm volatile("mbarrier.inval.shared.b64 [%0];" \
        :: "r"((uint32_t)(mbar)) : "memory")
#define MBARRIER_ARRIVE(mbar) \
    asm volatile("mbarrier.arrive.shared.b64 _, [%0];" \
        :: "r"((uint32_t)(mbar)) : "memory")
#define MBARRIER_WAIT_PARITY(mbar_smem_addr, phase_parity) do { \
    uint32_t _mbar = (uint32_t)(mbar_smem_addr); \
    uint32_t _parity = (uint32_t)(phase_parity); \
    uint32_t _done; \
    asm volatile( \
        "{\n\t.reg .pred p;\n\t" \
        "mbarrier.try_wait.parity.acquire.cta.shared::cta.b64 p, [%1], %2;\n\t" \
        "selp.b32 %0, 1, 0, p;\n\t}" \
        : "=r"(_done) : "r"(_mbar), "r"(_parity) : "memory"); \
    if (!_done) { \
        asm volatile( \
            "{\n\t.reg .pred P1;\n\t" \
            "WAIT_LOOP_%=:\n\t" \
            "mbarrier.try_wait.parity.acquire.cta.shared::cta.b64 P1, [%0], %1, 0x989680;\n\t" \
            "@P1 bra.uni WAIT_DONE_%=;\n\t" \
            "bra.uni WAIT_LOOP_%=;\n\t" \
            "WAIT_DONE_%=:\n\t}" \
            :: "r"(_mbar), "r"(_parity) : "memory"); \
    } \
} while(0)
#define FENCE_PROXY_ASYNC_SHARED_CTA() \
    asm volatile("fence.proxy.async.shared::cta;" ::: "memory")
#define CP_ASYNC16(smem_u32, gptr) \
    asm volatile("cp.async.cg.shared.global [%0], [%1], 16;" \
        :: "r"((uint32_t)(smem_u32)), "l"(gptr) : "memory")
#define CP_ASYNC_COMMIT() asm volatile("cp.async.commit_group;" ::: "memory")
#define CP_ASYNC_WAIT(n)  asm volatile("cp.async.wait_group %0;" :: "n"(n) : "memory")

#if HAS_TC
__device__ __forceinline__ uint32_t elect_one_pred() {
    uint32_t pred;
    asm volatile(
        "{\n\t.reg .pred p;\n\t"
        "elect.sync _|p, 0xFFFFFFFF;\n\t"
        "selp.b32 %0, 1, 0, p;\n\t}"
        : "=r"(pred));
    return pred;
}
#define TCGEN05_ALLOC(smem_result_addr, nCols) \
    asm volatile("tcgen05.alloc.cta_group::1.sync.aligned.shared::cta.b32 [%0], %1;" \
        :: "r"((uint32_t)(smem_result_addr)), "r"((uint32_t)(nCols)) : "memory")
#define TCGEN05_DEALLOC(tmem_addr, nCols) \
    asm volatile("tcgen05.dealloc.cta_group::1.sync.aligned.b32 %0, %1;" \
        :: "r"(tmem_addr), "r"((uint32_t)(nCols)))
#define TCGEN05_COMMIT(mbar) \
    asm volatile("tcgen05.commit.cta_group::1.mbarrier::arrive::one.shared::cluster.b64 [%0];" \
        :: "r"((uint32_t)(mbar)) : "memory")
#define TCGEN05_FENCE_AFTER() \
    asm volatile("tcgen05.fence::after_thread_sync;" ::: "memory")
#define TCGEN05_FENCE_BEFORE() \
    asm volatile("tcgen05.fence::before_thread_sync;" ::: "memory")
#define TCGEN05_WAIT_LD() \
    asm volatile("tcgen05.wait::ld.sync.aligned;" ::: "memory")
#define TCGEN05_LD_32X32B_X32(r, tmem_addr) \
    asm volatile( \
        "tcgen05.ld.sync.aligned.32x32b.x32.b32 " \
        "{%0, %1, %2, %3, %4, %5, %6, %7, " \
        " %8, %9, %10, %11, %12, %13, %14, %15, " \
        " %16, %17, %18, %19, %20, %21, %22, %23, " \
        " %24, %25, %26, %27, %28, %29, %30, %31}, [%32];" \
        : "=r"((r)[0]),  "=r"((r)[1]),  "=r"((r)[2]),  "=r"((r)[3]), \
          "=r"((r)[4]),  "=r"((r)[5]),  "=r"((r)[6]),  "=r"((r)[7]), \
          "=r"((r)[8]),  "=r"((r)[9]),  "=r"((r)[10]), "=r"((r)[11]), \
          "=r"((r)[12]), "=r"((r)[13]), "=r"((r)[14]), "=r"((r)[15]), \
          "=r"((r)[16]), "=r"((r)[17]), "=r"((r)[18]), "=r"((r)[19]), \
          "=r"((r)[20]), "=r"((r)[21]), "=r"((r)[22]), "=r"((r)[23]), \
          "=r"((r)[24]), "=r"((r)[25]), "=r"((r)[26]), "=r"((r)[27]), \
          "=r"((r)[28]), "=r"((r)[29]), "=r"((r)[30]), "=r"((r)[31]) \
        : "r"(tmem_addr))

static constexpr uint64_t SMEM_DESC_BASE_SW128 =
    (uint64_t(2)  << 61) | (uint64_t(1) << 46) | (uint64_t(64) << 32) | (uint64_t(1) << 16);
#define MAKE_SMEM_DESC(base_addr) \
    (SMEM_DESC_BASE_SW128 | ((uint64_t)((base_addr) >> 4) & 0x3FFF))

// idesc: dtype=F32, atype=BF16, btype=BF16, K-major/K-major, M=128, N=64
#define IDESC_M128N64 ((1u<<4)|(1u<<7)|(1u<<10)|((64u/8u)<<17)|((128u/16u)<<24))

__device__ __forceinline__ void mma_f16_ss(uint32_t d_tmem, uint64_t a_desc,
                                           uint64_t b_desc, uint32_t idesc, bool acc) {
    uint32_t en = acc ? 1u : 0u;
    asm volatile(
        "{\n\t.reg .pred p;\n\t"
        "setp.ne.u32 p, %5, 0;\n\t"
        "tcgen05.mma.cta_group::1.kind::f16 [%0], %1, %2, %3, {%4, %4, %4, %4}, p;\n\t}"
        :: "r"(d_tmem), "l"(a_desc), "l"(b_desc), "r"(idesc), "r"(0u), "r"(en)
        : "memory");
}
#endif // HAS_TC

#define SWZ128(off) ((off) ^ (((off) >> 3) & 0x70))

// ================= fp32 -> (hi,lo) bf16 split =================
__global__ __launch_bounds__(256)
void split_kernel(const float* __restrict__ in, __nv_bfloat16* __restrict__ hi,
                  __nv_bfloat16* __restrict__ lo, long long n4)
{
    long long i = (long long)blockIdx.x * 256 + threadIdx.x;
    if (i >= n4) return;
    float4 v = ((const float4*)in)[i];
    __nv_bfloat16 h0,h1,h2,h3,l0,l1,l2,l3;
    split2(v.x,h0,l0); split2(v.y,h1,l1); split2(v.z,h2,l2); split2(v.w,h3,l3);
    __nv_bfloat162* hp = (__nv_bfloat162*)(hi + 4*i);
    __nv_bfloat162* lp = (__nv_bfloat162*)(lo + 4*i);
    hp[0] = __nv_bfloat162(h0,h1); hp[1] = __nv_bfloat162(h2,h3);
    lp[0] = __nv_bfloat162(l0,l1); lp[1] = __nv_bfloat162(l2,l3);
}

// ================= GEMM: tcgen05 bf16x3, depth-4 half-tile pipeline ==========
// C[m,n] = scale*(sum_k A[m,k]*B[n,k] + bias[n]); tile 128(M) x 256(N), KT=64.
// 2 smem stages, each split into 2 K-halves -> 4 pipeline slots of 48KB.
// Warp 0: MMA issue. Warps 1-7: cp.async loaders with 2-group lag.
#define KT 64
#define STAGE_BYTES 98304
#define SMEM_TILE0 1024
#define GEMM_SMEM (SMEM_TILE0 + 2*STAGE_BYTES)   // 197632
// mbars: full[s] @ sb+8+8s (s=0..3, count 224); done[s] @ sb+40+8s (count 1)

__global__ __launch_bounds__(256) __cluster_dims__(1, 1, 1)
void gemm_tc_kernel(const __nv_bfloat16* __restrict__ Ah, const __nv_bfloat16* __restrict__ Al, int lda,
                    const __nv_bfloat16* __restrict__ Bh, const __nv_bfloat16* __restrict__ Bl, int ldb,
                    float* __restrict__ C, __nv_bfloat16* __restrict__ Ch, __nv_bfloat16* __restrict__ Cl,
                    int ldc, int K, const float* __restrict__ bias, float scale)
{
    extern __shared__ __align__(1024) char smem[];
    const int tid = threadIdx.x;
    const int n0 = blockIdx.x * 256;
    const int m0 = blockIdx.y * 128;

#if HAS_TC
    const uint32_t sb = smem_to_u32(smem);
    const int wid = tid >> 5, lid = tid & 31;

    if (wid == 0) { TCGEN05_ALLOC(sb + 0, 256); }
    if (tid == 0) {
#pragma unroll
        for (int s = 0; s < 4; s++) {
            MBARRIER_INIT(sb + 8 + s * 8, 224);   // full[s]
            MBARRIER_INIT(sb + 40 + s * 8, 1);    // done[s]
        }
    }
    __syncthreads();
    uint32_t tmem;
    asm volatile("ld.shared.b32 %0, [%1];" : "=r"(tmem) : "r"(sb));

    const int ktiles = K / KT;        // 32
    const int nh = 2 * ktiles;        // 64 half-tiles

    if (tid >= 32) {
        // ---------------- loader warps (224 threads), cp.async, 2-group lag ---------
        const int lt = tid - 32;
        for (int ht = 0; ht < nh; ht++) {
            const int slot = ht & 3;
            const int t = ht >> 1, h = ht & 1;
            if (ht >= 4) {
                MBARRIER_WAIT_PARITY(sb + 40 + slot * 8, ((ht >> 2) - 1) & 1);
            }
            const uint32_t st = sb + SMEM_TILE0 + (uint32_t)(slot >> 1) * STAGE_BYTES;
            const int k0 = t * KT + h * 32;
            // A hi/lo: 512 x 16B each (128 rows x 64B half)
            for (int i = lt; i < 512; i += 224) {
                int row = i >> 2, c = i & 3;
                uint32_t sw = SWZ128((uint32_t)(row * 128 + h * 64 + c * 16));
                CP_ASYNC16(st + sw,         Ah + (size_t)(m0 + row) * lda + k0 + c * 8);
                CP_ASYNC16(st + 16384 + sw, Al + (size_t)(m0 + row) * lda + k0 + c * 8);
            }
            // B hi/lo: 1024 x 16B each (256 rows x 64B half)
            for (int i = lt; i < 1024; i += 224) {
                int row = i >> 2, c = i & 3;
                uint32_t sw = SWZ128((uint32_t)(row * 128 + h * 64 + c * 16));
                CP_ASYNC16(st + 32768 + sw, Bh + (size_t)(n0 + row) * ldb + k0 + c * 8);
                CP_ASYNC16(st + 65536 + sw, Bl + (size_t)(n0 + row) * ldb + k0 + c * 8);
            }
            CP_ASYNC_COMMIT();
            if (ht >= 2) {
                CP_ASYNC_WAIT(2);   // group (ht-2) complete
                FENCE_PROXY_ASYNC_SHARED_CTA();
                MBARRIER_ARRIVE(sb + 8 + ((ht - 2) & 3) * 8);
            }
        }
        CP_ASYNC_WAIT(0);
        FENCE_PROXY_ASYNC_SHARED_CTA();
        MBARRIER_ARRIVE(sb + 8 + ((nh - 2) & 3) * 8);
        MBARRIER_ARRIVE(sb + 8 + ((nh - 1) & 3) * 8);
    } else if (elect_one_pred()) {
        // ---------------- MMA warp (single elected thread) ----------------
        for (int ht = 0; ht < nh; ht++) {
            const int slot = ht & 3;
            const int h = ht & 1;
            MBARRIER_WAIT_PARITY(sb + 8 + slot * 8, (ht >> 2) & 1);
            uint32_t sbase = sb + SMEM_TILE0 + (uint32_t)(slot >> 1) * STAGE_BYTES;
            uint64_t dAh = MAKE_SMEM_DESC(sbase);
            uint64_t dAl = MAKE_SMEM_DESC(sbase + 16384);
            uint64_t dBh = MAKE_SMEM_DESC(sbase + 32768);
            uint64_t dBl = MAKE_SMEM_DESC(sbase + 65536);
#pragma unroll
            for (int ks = 0; ks < 2; ks++) {
                uint64_t oa = (uint64_t)(h * 2 + ks) * 2;   // 32B K-steps in 16B units
#pragma unroll
                for (int p = 0; p < 3; p++) {
                    uint64_t da = (p == 2) ? dAl : dAh;
                    uint64_t db = (p == 1) ? dBl : dBh;
                    bool first = (ht == 0 && ks == 0 && p == 0);
#pragma unroll
                    for (int nq = 0; nq < 4; nq++) {
                        uint32_t d = tmem + nq * 64;
                        uint64_t ob = oa + nq * 512;
                        mma_f16_ss(d, da + oa, db + ob, IDESC_M128N64, !first);
                    }
                }
            }
            TCGEN05_COMMIT(sb + 40 + slot * 8);
        }
    }

    // all threads: wait final commit on each of the 4 slots
    {
        uint32_t ph = ((uint32_t)(ktiles >> 1) - 1) & 1;
#pragma unroll
        for (int s = 0; s < 4; s++) MBARRIER_WAIT_PARITY(sb + 40 + s * 8, ph);
    }
    TCGEN05_FENCE_AFTER();
    __syncthreads();

    // epilogue: warp w: rows m0 + (w&3)*32 .. +31, cols (w>>2)*128 .. +127
    const int row = m0 + (wid & 3) * 32 + lid;
    const int colbase = (wid >> 2) * 128;
#pragma unroll
    for (int cq = 0; cq < 4; cq++) {
        const int cb = colbase + cq * 32;
        uint32_t regs[32];
        TCGEN05_LD_32X32B_X32(regs, tmem + cb);
        TCGEN05_WAIT_LD();
        float v[32];
#pragma unroll
        for (int c = 0; c < 32; c++) {
            float bv = bias ? bias[n0 + cb + c] : 0.0f;
            v[c] = scale * (__uint_as_float(regs[c]) + bv);
        }
        if (C) {
            float* crow = C + (size_t)row * ldc + n0 + cb;
#pragma unroll
            for (int c4 = 0; c4 < 8; c4++) {
                *(float4*)(crow + c4 * 4) = make_float4(v[c4*4], v[c4*4+1], v[c4*4+2], v[c4*4+3]);
            }
        }
        if (Ch) {
            __nv_bfloat16 hv[32], lv[32];
#pragma unroll
            for (int c = 0; c < 32; c++) split2(v[c], hv[c], lv[c]);
            __nv_bfloat16* hrow = Ch + (size_t)row * ldc + n0 + cb;
            __nv_bfloat16* lrow = Cl + (size_t)row * ldc + n0 + cb;
#pragma unroll
            for (int c8 = 0; c8 < 4; c8++) {
                *(uint4*)(hrow + c8 * 8) = *(uint4*)&hv[c8 * 8];
                *(uint4*)(lrow + c8 * 8) = *(uint4*)&lv[c8 * 8];
            }
        }
    }
    TCGEN05_FENCE_BEFORE();
    __syncthreads();
    if (tid == 0) {
#pragma unroll
        for (int s = 0; s < 4; s++) { MBARRIER_INVAL(sb + 8 + s * 8); MBARRIER_INVAL(sb + 40 + s * 8); }
    }
    __syncthreads();
    if (wid == 0) { TCGEN05_DEALLOC(tmem, 256); }

#else  // ---------------- FMA fallback (256 threads; correctness-only path) ----------------
    (void)smem;
    const int tx = tid & 15, ty = tid >> 4;   // 16 x 16

    for (int half = 0; half < 2; half++) {
        const int nbase = n0 + half * 128;
        float acc[8][8];
#pragma unroll
        for (int i = 0; i < 8; i++)
#pragma unroll
            for (int j = 0; j < 8; j++) acc[i][j] = 0.0f;

        for (int k0 = 0; k0 < K; k0 += 16) {
#pragma unroll
            for (int kk = 0; kk < 16; kk++) {
                float a[8], b[8];
#pragma unroll
                for (int u = 0; u < 8; u++) {
                    size_t ia = (size_t)(m0 + ty * 8 + u) * lda + k0 + kk;
                    a[u] = __bfloat162float(Ah[ia]) + __bfloat162float(Al[ia]);
                }
#pragma unroll
                for (int u = 0; u < 8; u++) {
                    size_t ib = (size_t)(nbase + tx * 8 + u) * ldb + k0 + kk;
                    b[u] = __bfloat162float(Bh[ib]) + __bfloat162float(Bl[ib]);
                }
#pragma unroll
                for (int i = 0; i < 8; i++)
#pragma unroll
                    for (int j = 0; j < 8; j++)
                        acc[i][j] = fmaf(a[i], b[j], acc[i][j]);
            }
        }

        float bv[8];
#pragma unroll
        for (int j = 0; j < 8; j++) bv[j] = bias ? bias[nbase + tx * 8 + j] : 0.0f;
#pragma unroll
        for (int i = 0; i < 8; i++) {
            int r = m0 + ty * 8 + i;
            float v[8];
#pragma unroll
            for (int j = 0; j < 8; j++) v[j] = scale * (acc[i][j] + bv[j]);
            if (C) {
                float* crow = C + (size_t)r * ldc + nbase + tx * 8;
                *(float4*)(crow + 0) = make_float4(v[0], v[1], v[2], v[3]);
                *(float4*)(crow + 4) = make_float4(v[4], v[5], v[6], v[7]);
            }
            if (Ch) {
                __nv_bfloat16 hv[8], lv[8];
#pragma unroll
                for (int j = 0; j < 8; j++) split2(v[j], hv[j], lv[j]);
                *(uint4*)(Ch + (size_t)r * ldc + nbase + tx * 8) = *(uint4*)hv;
                *(uint4*)(Cl + (size_t)r * ldc + nbase + tx * 8) = *(uint4*)lv;
            }
        }
    }
#endif
}

// ================= attention kernels =================
// V is read as hi+lo bf16 (fp32 qkv no longer materialized)
__device__ __forceinline__ float4 load_v4(const __nv_bfloat16* vh, const __nv_bfloat16* vl,
                                          size_t idx)
{
    __nv_bfloat162 h0 = *(const __nv_bfloat162*)(vh + idx);
    __nv_bfloat162 h1 = *(const __nv_bfloat162*)(vh + idx + 2);
    __nv_bfloat162 l0 = *(const __nv_bfloat162*)(vl + idx);
    __nv_bfloat162 l1 = *(const __nv_bfloat162*)(vl + idx + 2);
    float2 fh0 = __bfloat1622float2(h0), fh1 = __bfloat1622float2(h1);
    float2 fl0 = __bfloat1622float2(l0), fl1 = __bfloat1622float2(l1);
    return make_float4(fh0.x + fl0.x, fh0.y + fl0.y, fh1.x + fl1.x, fh1.y + fl1.y);
}

__global__ __launch_bounds__(256)
void chunk_kv_kernel()
{
    __shared__ float Ks[16][TP];
    __shared__ float Vs[16][TP];
    const int c = blockIdx.x, h = blockIdx.y, b = blockIdx.z;
    const int tid = threadIdx.x;
    const int tx = tid & 15, ty = tid >> 4;
    const float s = head_slope(h);

    const float* kbase = g_ke + ((size_t)(b * SEQ + c * CHUNKL)) * DMODEL + h * DHEAD;
    const __nv_bfloat16* vh = g_qkv_h + ((size_t)(b * SEQ + c * CHUNKL)) * NQKV + 4096 + h * DHEAD;
    const __nv_bfloat16* vl = g_qkv_l + ((size_t)(b * SEQ + c * CHUNKL)) * NQKV + 4096 + h * DHEAD;

    float acc[8][8];
#pragma unroll
    for (int i = 0; i < 8; i++)
#pragma unroll
        for (int j = 0; j < 8; j++) acc[i][j] = 0.0f;

    for (int j0 = 0; j0 < CHUNKL; j0 += 16) {
#pragma unroll
        for (int it = 0; it < 2; it++) {
            int f   = tid + it * 256;
            int row = f >> 5;
            int c4  = (f & 31) * 4;
            int j   = j0 + row;
            float kd = expf(-s * (float)(CHUNKL - 1 - j));
            float4 kv = *(const float4*)(kbase + (size_t)j * DMODEL + c4);
            kv.x *= kd; kv.y *= kd; kv.z *= kd; kv.w *= kd;
            *(float4*)&Ks[row][c4] = kv;
            *(float4*)&Vs[row][c4] = load_v4(vh, vl, (size_t)j * NQKV + c4);
        }
        __syncthreads();
#pragma unroll
        for (int kk = 0; kk < 16; kk++) {
            float a[8], bb[8];
#pragma unroll
            for (int u = 0; u < 8; u++) a[u]  = Ks[kk][ty * 8 + u];
#pragma unroll
            for (int u = 0; u < 8; u++) bb[u] = Vs[kk][tx * 8 + u];
#pragma unroll
            for (int i = 0; i < 8; i++)
#pragma unroll
                for (int j = 0; j < 8; j++)
                    acc[i][j] = fmaf(a[i], bb[j], acc[i][j]);
        }
        __syncthreads();
    }

    float* gout = g_st + ((size_t)((b * NHEAD + h) * NCHUNK + c)) * (128 * 128);
#pragma unroll
    for (int i = 0; i < 8; i++) {
        float* row = gout + (size_t)(ty * 8 + i) * 128 + tx * 8;
        *(float4*)(row + 0) = make_float4(acc[i][0], acc[i][1], acc[i][2], acc[i][3]);
        *(float4*)(row + 4) = make_float4(acc[i][4], acc[i][5], acc[i][6], acc[i][7]);
    }
}

__global__ __launch_bounds__(256)
void scan_kernel()
{
    const int bh = blockIdx.y;
    const int h  = bh & (NHEAD - 1);
    const float s   = head_slope(h);
    const float lam = expf(-s * (float)CHUNKL);
    const int e = blockIdx.x * 256 + threadIdx.x;
    float* base = g_st + (size_t)bh * NCHUNK * (128 * 128) + e;
    float S = 0.0f;
#pragma unroll 4
    for (int c = 0; c < NCHUNK; c++) {
        float g = base[(size_t)c * (128 * 128)];
        base[(size_t)c * (128 * 128)] = S;
        S = fmaf(lam, S, g);
    }
}

__global__ __launch_bounds__(256)
void chunk_out_kernel()
{
    extern __shared__ float sm[];
    float* Ash = sm;
    float* T1  = sm + 128 * APITCH;
    float* T2  = T1 + 16 * TP;

    const int c = blockIdx.x, hh = blockIdx.y, b = blockIdx.z;
    const int tid = threadIdx.x;
    const int tx = tid & 15, ty = tid >> 4;
    const float s = head_slope(hh);

    const size_t tok0 = (size_t)(b * SEQ + c * CHUNKL);
    const float* qbase = g_qe + tok0 * DMODEL + hh * DHEAD;
    const float* kbase = g_ke + tok0 * DMODEL + hh * DHEAD;
    const __nv_bfloat16* vh = g_qkv_h + tok0 * NQKV + 4096 + hh * DHEAD;
    const __nv_bfloat16* vl = g_qkv_l + tok0 * NQKV + 4096 + hh * DHEAD;
    const float* Sbase = g_st + ((size_t)((b * NHEAD + hh) * NCHUNK + c)) * (128 * 128);

    float acc[8][8];
#pragma unroll
    for (int i = 0; i < 8; i++)
#pragma unroll
        for (int j = 0; j < 8; j++) acc[i][j] = 0.0f;

    for (int d0 = 0; d0 < DHEAD; d0 += 16) {
#pragma unroll
        for (int it = 0; it < 2; it++) {
            int f   = tid + it * 256;
            int row = f >> 2;
            int kq  = (f & 3) * 4;
            float4 qv = *(const float4*)(qbase + (size_t)row * DMODEL + d0 + kq);
            T1[(kq + 0) * TP + row] = qv.x; T1[(kq + 1) * TP + row] = qv.y;
            T1[(kq + 2) * TP + row] = qv.z; T1[(kq + 3) * TP + row] = qv.w;
            float4 kv = *(const float4*)(kbase + (size_t)row * DMODEL + d0 + kq);
            T2[(kq + 0) * TP + row] = kv.x; T2[(kq + 1) * TP + row] = kv.y;
            T2[(kq + 2) * TP + row] = kv.z; T2[(kq + 3) * TP + row] = kv.w;
        }
        __syncthreads();
#pragma unroll
        for (int kk = 0; kk < 16; kk++) {
            float a[8], bb[8];
#pragma unroll
            for (int u = 0; u < 8; u++) a[u]  = T1[kk * TP + ty * 8 + u];
#pragma unroll
            for (int u = 0; u < 8; u++) bb[u] = T2[kk * TP + tx * 8 + u];
#pragma unroll
            for (int i = 0; i < 8; i++)
#pragma unroll
                for (int j = 0; j < 8; j++)
                    acc[i][j] = fmaf(a[i], bb[j], acc[i][j]);
        }
        __syncthreads();
    }

#pragma unroll
    for (int jj = 0; jj < 8; jj++) {
#pragma unroll
        for (int ii = 0; ii < 8; ii++) {
            int i = ty * 8 + ii, j = tx * 8 + jj;
            float v = (i >= j) ? acc[ii][jj] * expf(-s * (float)(i - j)) : 0.0f;
            Ash[j * APITCH + i] = v;
        }
    }
    __syncthreads();

    float accO[8][8];
#pragma unroll
    for (int i = 0; i < 8; i++)
#pragma unroll
        for (int j = 0; j < 8; j++) accO[i][j] = 0.0f;

    for (int j0 = 0; j0 < CHUNKL; j0 += 16) {
#pragma unroll
        for (int it = 0; it < 2; it++) {
            int f   = tid + it * 256;
            int row = f >> 5;
            int c4  = (f & 31) * 4;
            *(float4*)&T1[row * TP + c4] = load_v4(vh, vl, (size_t)(j0 + row) * NQKV + c4);
        }
        __syncthreads();
#pragma unroll
        for (int kk = 0; kk < 16; kk++) {
            float a[8], bb[8];
#pragma unroll
            for (int u = 0; u < 8; u++) a[u]  = Ash[(j0 + kk) * APITCH + ty * 8 + u];
#pragma unroll
            for (int u = 0; u < 8; u++) bb[u] = T1[kk * TP + tx * 8 + u];
#pragma unroll
            for (int i = 0; i < 8; i++)
#pragma unroll
                for (int j = 0; j < 8; j++)
                    accO[i][j] = fmaf(a[i], bb[j], accO[i][j]);
        }
        __syncthreads();
    }

    float acc2[8][8];
#pragma unroll
    for (int i = 0; i < 8; i++)
#pragma unroll
        for (int j = 0; j < 8; j++) acc2[i][j] = 0.0f;

    for (int d0 = 0; d0 < DHEAD; d0 += 16) {
#pragma unroll
        for (int it = 0; it < 2; it++) {
            int f   = tid + it * 256;
            int row = f >> 2;
            int kq  = (f & 3) * 4;
            float4 qv = *(const float4*)(qbase + (size_t)row * DMODEL + d0 + kq);
            T1[(kq + 0) * TP + row] = qv.x; T1[(kq + 1) * TP + row] = qv.y;
            T1[(kq + 2) * TP + row] = qv.z; T1[(kq + 3) * TP + row] = qv.w;
        }
#pragma unroll
        for (int it = 0; it < 2; it++) {
            int f   = tid + it * 256;
            int row = f >> 5;
            int c4  = (f & 31) * 4;
            float4 sv = *(const float4*)(Sbase + (size_t)(d0 + row) * 128 + c4);
            *(float4*)&T2[row * TP + c4] = sv;
        }
        __syncthreads();
#pragma unroll
        for (int kk = 0; kk < 16; kk++) {
            float a[8], bb[8];
#pragma unroll
            for (int u = 0; u < 8; u++) a[u]  = T1[kk * TP + ty * 8 + u];
#pragma unroll
            for (int u = 0; u < 8; u++) bb[u] = T2[kk * TP + tx * 8 + u];
#pragma unroll
            for (int i = 0; i < 8; i++)
#pragma unroll
                for (int j = 0; j < 8; j++)
                    acc2[i][j] = fmaf(a[i], bb[j], acc2[i][j]);
        }
        __syncthreads();
    }

    float vals[8][8];
#pragma unroll
    for (int ii = 0; ii < 8; ii++) {
        float qd = expf(-s * (float)(ty * 8 + ii + 1));
#pragma unroll
        for (int jj = 0; jj < 8; jj++)
            vals[ii][jj] = accO[ii][jj] + qd * acc2[ii][jj];
    }

#pragma unroll
    for (int ii = 0; ii < 8; ii++) {
        float ps = 0.0f, pq = 0.0f;
#pragma unroll
        for (int jj = 0; jj < 8; jj++) { float v = vals[ii][jj]; ps += v; pq += v * v; }
        T1[(ty * 8 + ii) * 16 + tx] = ps;
        T2[(ty * 8 + ii) * 16 + tx] = pq;
    }
    __syncthreads();

    if (tid < 128) {
        float s1 = 0.0f, s2 = 0.0f;
#pragma unroll
        for (int t = 0; t < 16; t++) { s1 += T1[tid * 16 + t]; s2 += T2[tid * 16 + t]; }
        float mu  = s1 * (1.0f / 128.0f);
        float var = s2 * (1.0f / 128.0f) - mu * mu;
        Ash[tid]       = mu;
        Ash[128 + tid] = rsqrtf(var + 1e-5f);
    }
    __syncthreads();

    float* obase = g_y + tok0 * DMODEL + hh * DHEAD;
    __nv_bfloat16* ohbase = g_y_h + tok0 * DMODEL + hh * DHEAD;
    __nv_bfloat16* olbase = g_y_l + tok0 * DMODEL + hh * DHEAD;
#pragma unroll
    for (int ii = 0; ii < 8; ii++) {
        int i = ty * 8 + ii;
        float mu = Ash[i], rs = Ash[128 + i];
        float o[8];
#pragma unroll
        for (int jj = 0; jj < 8; jj++) o[jj] = (vals[ii][jj] - mu) * rs;
        float* row = obase + (size_t)i * DMODEL + tx * 8;
        *(float4*)(row + 0) = make_float4(o[0], o[1], o[2], o[3]);
        *(float4*)(row + 4) = make_float4(o[4], o[5], o[6], o[7]);
        __nv_bfloat16 hv[8], lv[8];
#pragma unroll
        for (int jj = 0; jj < 8; jj++) split2(o[jj], hv[jj], lv[jj]);
        *(uint4*)(ohbase + (size_t)i * DMODEL + tx * 8) = *(uint4*)hv;
        *(uint4*)(olbase + (size_t)i * DMODEL + tx * 8) = *(uint4*)lv;
    }
}

// ================= host launcher =================
extern "C" void kernel_launch(void* const* d_in, const int* in_sizes, int n_in,
                              void* d_out, int out_size)
{
    (void)in_sizes; (void)n_in; (void)out_size;
    const float* x       = (const float*)d_in[0];
    const float* W_in    = (const float*)d_in[1];
    const float* W_embed = (const float*)d_in[2];
    const float* b_embed = (const float*)d_in[3];
    const float* W_out   = (const float*)d_in[4];
    float* out = (float*)d_out;

    float *qe, *ke, *y;
    __nv_bfloat16 *qkv_h, *qkv_l, *x_h, *x_l, *win_h, *win_l, *wemb_h, *wemb_l, *wout_h, *wout_l, *y_h, *y_l;
    cudaGetSymbolAddress((void**)&qe,    g_qe);
    cudaGetSymbolAddress((void**)&ke,    g_ke);
    cudaGetSymbolAddress((void**)&y,     g_y);
    cudaGetSymbolAddress((void**)&qkv_h, g_qkv_h);
    cudaGetSymbolAddress((void**)&qkv_l, g_qkv_l);
    cudaGetSymbolAddress((void**)&x_h,   g_x_h);
    cudaGetSymbolAddress((void**)&x_l,   g_x_l);
    cudaGetSymbolAddress((void**)&win_h, g_win_h);
    cudaGetSymbolAddress((void**)&win_l, g_win_l);
    cudaGetSymbolAddress((void**)&wemb_h,g_wemb_h);
    cudaGetSymbolAddress((void**)&wemb_l,g_wemb_l);
    cudaGetSymbolAddress((void**)&wout_h,g_wout_h);
    cudaGetSymbolAddress((void**)&wout_l,g_wout_l);
    cudaGetSymbolAddress((void**)&y_h,   g_y_h);
    cudaGetSymbolAddress((void**)&y_l,   g_y_l);

    const int smem_k5 = (128 * APITCH + 2 * 16 * TP) * 4;
    cudaFuncSetAttribute(chunk_out_kernel, cudaFuncAttributeMaxDynamicSharedMemorySize, smem_k5);
    cudaFuncSetAttribute(gemm_tc_kernel, cudaFuncAttributeMaxDynamicSharedMemorySize, GEMM_SMEM);

    // splits
    {
        long long n4;
        n4 = (long long)NTOK * DMODEL / 4;
        split_kernel<<<(unsigned)((n4 + 255) / 256), 256>>>(x, x_h, x_l, n4);
        n4 = (long long)NQKV * DMODEL / 4;
        split_kernel<<<(unsigned)((n4 + 255) / 256), 256>>>(W_in, win_h, win_l, n4);
        n4 = (long long)DMODEL * DMODEL / 4;
        split_kernel<<<(unsigned)((n4 + 255) / 256), 256>>>(W_embed, wemb_h, wemb_l, n4);
        split_kernel<<<(unsigned)((n4 + 255) / 256), 256>>>(W_out, wout_h, wout_l, n4);
    }

    // 1) qkv = x @ W_in^T  (bf16 hi/lo only; fp32 not materialized)
    gemm_tc_kernel<<<dim3(NQKV / 256, NTOK / 128), 256, GEMM_SMEM>>>(
        x_h, x_l, DMODEL, win_h, win_l, DMODEL,
        nullptr, qkv_h, qkv_l, NQKV, DMODEL, nullptr, 1.0f);

    // 2) qe = qkv[:,0:2048] @ W_embed^T + b
    gemm_tc_kernel<<<dim3(DMODEL / 256, NTOK / 128), 256, GEMM_SMEM>>>(
        qkv_h, qkv_l, NQKV, wemb_h, wemb_l, DMODEL,
        qe, nullptr, nullptr, DMODEL, DMODEL, b_embed, 1.0f);

    // 3) ke = (qkv[:,2048:4096] @ W_embed^T + b) * QK_SCALE
    gemm_tc_kernel<<<dim3(DMODEL / 256, NTOK / 128), 256, GEMM_SMEM>>>(
        qkv_h + 2048, qkv_l + 2048, NQKV, wemb_h, wemb_l, DMODEL,
        ke, nullptr, nullptr, DMODEL, DMODEL, b_embed, QK_SCALE);

    // 4) per-chunk KV products
    chunk_kv_kernel<<<dim3(NCHUNK, NHEAD, BATCH), 256>>>();

    // 5) state scan
    scan_kernel<<<dim3(128 * 128 / 256, BATCH * NHEAD), 256>>>();

    // 6) per-chunk output + fused LayerNorm (+ bf16 split of y)
    chunk_out_kernel<<<dim3(NCHUNK, NHEAD, BATCH), 256, smem_k5>>>();

    // 7) out = y @ W_out^T
    gemm_tc_kernel<<<dim3(DMODEL / 256, NTOK / 128), 256, GEMM_SMEM>>>(
        y_h, y_l, DMODEL, wout_h, wout_l, DMODEL,
        out, nullptr, nullptr, DMODEL, DMODEL, nullptr, 1.0f);
}

// round 15
// speedup vs baseline: 5.4192x; 1.3651x over previous
#include <cuda_runtime.h>
#include <cuda_bf16.h>
#include <math.h>
#include <stdint.h>

// ---------------- problem constants ----------------
#define BATCH   2
#define SEQ     8192
#define NTOK    (BATCH*SEQ)        // 16384
#define DMODEL  2048
#define NQKV    6144
#define NHEAD   16
#define DHEAD   128
#define NCHUNK  64
#define CHUNKL  128
#define QK_SCALE 0.08838834764831845f

#define TP 132
#define APITCH 129

#if defined(__CUDA_ARCH__) && (defined(__CUDA_ARCH_FEAT_SM103_ALL) || defined(__CUDA_ARCH_FEAT_SM100_ALL) || defined(__CUDA_ARCH_FEAT_SM101_ALL) || defined(__CUDA_ARCH_FAMILY_SPECIFIC__) || defined(__CUDA_ARCH_SPECIFIC__))
#define HAS_TC 1
#else
#define HAS_TC 0
#endif

// ---------------- device scratch ----------------
__device__ __nv_bfloat16 g_qkv_h[(size_t)NTOK * NQKV];
__device__ __nv_bfloat16 g_qkv_l[(size_t)NTOK * NQKV];
__device__ float g_qe [(size_t)NTOK * DMODEL];
__device__ float g_ke [(size_t)NTOK * DMODEL];
__device__ float g_st [(size_t)BATCH * NHEAD * NCHUNK * 128 * 128];
__device__ float g_y  [(size_t)NTOK * DMODEL];
__device__ __nv_bfloat16 g_y_h[(size_t)NTOK * DMODEL];
__device__ __nv_bfloat16 g_y_l[(size_t)NTOK * DMODEL];
__device__ __nv_bfloat16 g_x_h[(size_t)NTOK * DMODEL];
__device__ __nv_bfloat16 g_x_l[(size_t)NTOK * DMODEL];
__device__ __nv_bfloat16 g_win_h[(size_t)NQKV * DMODEL];
__device__ __nv_bfloat16 g_win_l[(size_t)NQKV * DMODEL];
__device__ __nv_bfloat16 g_wemb_h[(size_t)DMODEL * DMODEL];
__device__ __nv_bfloat16 g_wemb_l[(size_t)DMODEL * DMODEL];
__device__ __nv_bfloat16 g_wout_h[(size_t)DMODEL * DMODEL];
__device__ __nv_bfloat16 g_wout_l[(size_t)DMODEL * DMODEL];

__device__ __forceinline__ float head_slope(int h) {
    return -logf(1.0f - exp2f(-5.0f - (float)h));
}

__device__ __forceinline__ void split2(float v, __nv_bfloat16& h, __nv_bfloat16& l) {
    h = __float2bfloat16_rn(v);
    l = __float2bfloat16_rn(v - __bfloat162float(h));
}

// ================= PTX helpers =================
__device__ __forceinline__ uint32_t smem_to_u32(const void* p) {
    uint32_t a;
    asm("{ .reg .u64 t; cvta.to.shared.u64 t, %1; cvt.u32.u64 %0, t; }" : "=r"(a) : "l"(p));
    return a;
}
#define MBARRIER_INIT(mbar, count) \
    asm volatile("mbarrier.init.shared.b64 [%0], %1;" \
        :: "r"((uint32_t)(mbar)), "r"((uint32_t)(count)) : "memory")
#define MBARRIER_INVAL(mbar) \
    asm volatile("mbarrier.inval.shared.b64 [%0];" \
        :: "r"((uint32_t)(mbar)) : "memory")
#define MBARRIER_ARRIVE(mbar) \
    asm volatile("mbarrier.arrive.shared.b64 _, [%0];" \
        :: "r"((uint32_t)(mbar)) : "memory")
#define MBARRIER_WAIT_PARITY(mbar_smem_addr, phase_parity) do { \
    uint32_t _mbar = (uint32_t)(mbar_smem_addr); \
    uint32_t _parity = (uint32_t)(phase_parity); \
    uint32_t _done; \
    asm volatile( \
        "{\n\t.reg .pred p;\n\t" \
        "mbarrier.try_wait.parity.acquire.cta.shared::cta.b64 p, [%1], %2;\n\t" \
        "selp.b32 %0, 1, 0, p;\n\t}" \
        : "=r"(_done) : "r"(_mbar), "r"(_parity) : "memory"); \
    if (!_done) { \
        asm volatile( \
            "{\n\t.reg .pred P1;\n\t" \
            "WAIT_LOOP_%=:\n\t" \
            "mbarrier.try_wait.parity.acquire.cta.shared::cta.b64 P1, [%0], %1, 0x989680;\n\t" \
            "@P1 bra.uni WAIT_DONE_%=;\n\t" \
            "bra.uni WAIT_LOOP_%=;\n\t" \
            "WAIT_DONE_%=:\n\t}" \
            :: "r"(_mbar), "r"(_parity) : "memory"); \
    } \
} while(0)
#define FENCE_PROXY_ASYNC_SHARED_CTA() \
    asm volatile("fence.proxy.async.shared::cta;" ::: "memory")
#define CP_ASYNC16(smem_u32, gptr) \
    asm volatile("cp.async.cg.shared.global [%0], [%1], 16;" \
        :: "r"((uint32_t)(smem_u32)), "l"(gptr) : "memory")
#define CP_ASYNC_COMMIT() asm volatile("cp.async.commit_group;" ::: "memory")
#define CP_ASYNC_WAIT(n)  asm volatile("cp.async.wait_group %0;" :: "n"(n) : "memory")

#if HAS_TC
__device__ __forceinline__ uint32_t elect_one_pred() {
    uint32_t pred;
    asm volatile(
        "{\n\t.reg .pred p;\n\t"
        "elect.sync _|p, 0xFFFFFFFF;\n\t"
        "selp.b32 %0, 1, 0, p;\n\t}"
        : "=r"(pred));
    return pred;
}
#define TCGEN05_ALLOC(smem_result_addr, nCols) \
    asm volatile("tcgen05.alloc.cta_group::1.sync.aligned.shared::cta.b32 [%0], %1;" \
        :: "r"((uint32_t)(smem_result_addr)), "r"((uint32_t)(nCols)) : "memory")
#define TCGEN05_DEALLOC(tmem_addr, nCols) \
    asm volatile("tcgen05.dealloc.cta_group::1.sync.aligned.b32 %0, %1;" \
        :: "r"(tmem_addr), "r"((uint32_t)(nCols)))
#define TCGEN05_COMMIT(mbar) \
    asm volatile("tcgen05.commit.cta_group::1.mbarrier::arrive::one.shared::cluster.b64 [%0];" \
        :: "r"((uint32_t)(mbar)) : "memory")
#define TCGEN05_FENCE_AFTER() \
    asm volatile("tcgen05.fence::after_thread_sync;" ::: "memory")
#define TCGEN05_FENCE_BEFORE() \
    asm volatile("tcgen05.fence::before_thread_sync;" ::: "memory")
#define TCGEN05_WAIT_LD() \
    asm volatile("tcgen05.wait::ld.sync.aligned;" ::: "memory")
#define TCGEN05_LD_32X32B_X32(r, tmem_addr) \
    asm volatile( \
        "tcgen05.ld.sync.aligned.32x32b.x32.b32 " \
        "{%0, %1, %2, %3, %4, %5, %6, %7, " \
        " %8, %9, %10, %11, %12, %13, %14, %15, " \
        " %16, %17, %18, %19, %20, %21, %22, %23, " \
        " %24, %25, %26, %27, %28, %29, %30, %31}, [%32];" \
        : "=r"((r)[0]),  "=r"((r)[1]),  "=r"((r)[2]),  "=r"((r)[3]), \
          "=r"((r)[4]),  "=r"((r)[5]),  "=r"((r)[6]),  "=r"((r)[7]), \
          "=r"((r)[8]),  "=r"((r)[9]),  "=r"((r)[10]), "=r"((r)[11]), \
          "=r"((r)[12]), "=r"((r)[13]), "=r"((r)[14]), "=r"((r)[15]), \
          "=r"((r)[16]), "=r"((r)[17]), "=r"((r)[18]), "=r"((r)[19]), \
          "=r"((r)[20]), "=r"((r)[21]), "=r"((r)[22]), "=r"((r)[23]), \
          "=r"((r)[24]), "=r"((r)[25]), "=r"((r)[26]), "=r"((r)[27]), \
          "=r"((r)[28]), "=r"((r)[29]), "=r"((r)[30]), "=r"((r)[31]) \
        : "r"(tmem_addr))

static constexpr uint64_t SMEM_DESC_BASE_SW128 =
    (uint64_t(2)  << 61) | (uint64_t(1) << 46) | (uint64_t(64) << 32) | (uint64_t(1) << 16);
#define MAKE_SMEM_DESC(base_addr) \
    (SMEM_DESC_BASE_SW128 | ((uint64_t)((base_addr) >> 4) & 0x3FFF))

// idesc: dtype=F32, atype=BF16, btype=BF16, K-major/K-major, M=128, N=64
#define IDESC_M128N64 ((1u<<4)|(1u<<7)|(1u<<10)|((64u/8u)<<17)|((128u/16u)<<24))

__device__ __forceinline__ void mma_f16_ss(uint32_t d_tmem, uint64_t a_desc,
                                           uint64_t b_desc, uint32_t idesc, bool acc) {
    uint32_t en = acc ? 1u : 0u;
    asm volatile(
        "{\n\t.reg .pred p;\n\t"
        "setp.ne.u32 p, %5, 0;\n\t"
        "tcgen05.mma.cta_group::1.kind::f16 [%0], %1, %2, %3, {%4, %4, %4, %4}, p;\n\t}"
        :: "r"(d_tmem), "l"(a_desc), "l"(b_desc), "r"(idesc), "r"(0u), "r"(en)
        : "memory");
}
#endif // HAS_TC

#define SWZ128(off) ((off) ^ (((off) >> 3) & 0x70))

// ================= fp32 -> (hi,lo) bf16 split =================
__global__ __launch_bounds__(256)
void split_kernel(const float* __restrict__ in, __nv_bfloat16* __restrict__ hi,
                  __nv_bfloat16* __restrict__ lo, long long n4)
{
    long long i = (long long)blockIdx.x * 256 + threadIdx.x;
    if (i >= n4) return;
    float4 v = ((const float4*)in)[i];
    __nv_bfloat16 h0,h1,h2,h3,l0,l1,l2,l3;
    split2(v.x,h0,l0); split2(v.y,h1,l1); split2(v.z,h2,l2); split2(v.w,h3,l3);
    __nv_bfloat162* hp = (__nv_bfloat162*)(hi + 4*i);
    __nv_bfloat162* lp = (__nv_bfloat162*)(lo + 4*i);
    hp[0] = __nv_bfloat162(h0,h1); hp[1] = __nv_bfloat162(h2,h3);
    lp[0] = __nv_bfloat162(l0,l1); lp[1] = __nv_bfloat162(l2,l3);
}

// ================= GEMM: tcgen05 bf16x3, 256x256 tile, ring of 4 K-quarter slots ==
// C[m,n] = scale*(sum_k A[m,k]*B[n,k] + bias[n]); tile 256(M) x 256(N).
// Buffers (SW128, 128B rows): Ah 32KB | Al 32KB | Bh 32KB | Bl 32KB = 128KB.
// Slot = one K-step of 16 elems (32B column-quarter of the 128B rows), ring of 4.
// Warp 0: MMA issue. Warps 1-7: cp.async loaders with 2-group lag.
#define SMEM_TILE0 1024
#define A_OFF  0
#define AL_OFF 32768
#define B_OFF  65536
#define BL_OFF 98304
#define GEMM_SMEM (SMEM_TILE0 + 131072)   // 132096
// mbars: full[s] @ sb+8+8s (s=0..3, count 224); done[s] @ sb+40+8s (count 1)

__global__ __launch_bounds__(256) __cluster_dims__(1, 1, 1)
void gemm_tc_kernel(const __nv_bfloat16* __restrict__ Ah, const __nv_bfloat16* __restrict__ Al, int lda,
                    const __nv_bfloat16* __restrict__ Bh, const __nv_bfloat16* __restrict__ Bl, int ldb,
                    float* __restrict__ C, __nv_bfloat16* __restrict__ Ch, __nv_bfloat16* __restrict__ Cl,
                    int ldc, int K, const float* __restrict__ bias, float scale)
{
    extern __shared__ __align__(1024) char smem[];
    const int tid = threadIdx.x;
    const int n0 = blockIdx.x * 256;
    const int m0 = blockIdx.y * 256;

#if HAS_TC
    const uint32_t sb = smem_to_u32(smem);
    const int wid = tid >> 5, lid = tid & 31;

    if (wid == 0) { TCGEN05_ALLOC(sb + 0, 512); }
    if (tid == 0) {
#pragma unroll
        for (int s = 0; s < 4; s++) {
            MBARRIER_INIT(sb + 8 + s * 8, 224);   // full[s]
            MBARRIER_INIT(sb + 40 + s * 8, 1);    // done[s]
        }
    }
    __syncthreads();
    uint32_t tmem;
    asm volatile("ld.shared.b32 %0, [%1];" : "=r"(tmem) : "r"(sb));

    const int NQ = K / 16;            // 128 K-steps
    const uint32_t stA  = sb + SMEM_TILE0 + A_OFF;
    const uint32_t stAl = sb + SMEM_TILE0 + AL_OFF;
    const uint32_t stB  = sb + SMEM_TILE0 + B_OFF;
    const uint32_t stBl = sb + SMEM_TILE0 + BL_OFF;

    if (tid >= 32) {
        // ---------------- loader warps (224 threads), cp.async, 2-group lag ---------
        const int lt = tid - 32;
        for (int gq = 0; gq < NQ; gq++) {
            const int slot = gq & 3;
            if (gq >= 4) {
                MBARRIER_WAIT_PARITY(sb + 40 + slot * 8, ((gq >> 2) - 1) & 1);
            }
            const int qq = slot;             // column-quarter within the 128B rows
            const int k0 = gq * 16;
            // A hi/lo: 256 rows x 32B each -> 512 x 16B chunks per operand
            for (int i = lt; i < 512; i += 224) {
                int row = i >> 1, c = i & 1;
                uint32_t sw = SWZ128((uint32_t)(row * 128 + qq * 32 + c * 16));
                CP_ASYNC16(stA  + sw, Ah + (size_t)(m0 + row) * lda + k0 + c * 8);
                CP_ASYNC16(stAl + sw, Al + (size_t)(m0 + row) * lda + k0 + c * 8);
            }
            // B hi/lo: 256 rows x 32B each
            for (int i = lt; i < 512; i += 224) {
                int row = i >> 1, c = i & 1;
                uint32_t sw = SWZ128((uint32_t)(row * 128 + qq * 32 + c * 16));
                CP_ASYNC16(stB  + sw, Bh + (size_t)(n0 + row) * ldb + k0 + c * 8);
                CP_ASYNC16(stBl + sw, Bl + (size_t)(n0 + row) * ldb + k0 + c * 8);
            }
            CP_ASYNC_COMMIT();
            if (gq >= 2) {
                CP_ASYNC_WAIT(2);   // group (gq-2) complete
                FENCE_PROXY_ASYNC_SHARED_CTA();
                MBARRIER_ARRIVE(sb + 8 + ((gq - 2) & 3) * 8);
            }
        }
        CP_ASYNC_WAIT(0);
        FENCE_PROXY_ASYNC_SHARED_CTA();
        MBARRIER_ARRIVE(sb + 8 + ((NQ - 2) & 3) * 8);
        MBARRIER_ARRIVE(sb + 8 + ((NQ - 1) & 3) * 8);
    } else if (elect_one_pred()) {
        // ---------------- MMA warp (single elected thread) ----------------
        uint64_t dAh = MAKE_SMEM_DESC(stA);
        uint64_t dAl = MAKE_SMEM_DESC(stAl);
        uint64_t dBh = MAKE_SMEM_DESC(stB);
        uint64_t dBl = MAKE_SMEM_DESC(stBl);
        for (int gq = 0; gq < NQ; gq++) {
            const int slot = gq & 3;
            MBARRIER_WAIT_PARITY(sb + 8 + slot * 8, (gq >> 2) & 1);
            const uint64_t oq = (uint64_t)slot * 2;   // 32B quarter in 16B units
#pragma unroll
            for (int p = 0; p < 3; p++) {
                uint64_t da = (p == 2) ? dAl : dAh;
                uint64_t db = (p == 1) ? dBl : dBh;
                bool first = (gq == 0 && p == 0);
#pragma unroll
                for (int mb = 0; mb < 2; mb++) {
                    uint64_t oa = oq + (uint64_t)mb * 1024;   // +128 rows*128B
#pragma unroll
                    for (int nq = 0; nq < 4; nq++) {
                        uint32_t d = tmem + mb * 256 + nq * 64;
                        uint64_t ob = oq + (uint64_t)nq * 512; // +64 rows*128B
                        mma_f16_ss(d, da + oa, db + ob, IDESC_M128N64, !first);
                    }
                }
            }
            TCGEN05_COMMIT(sb + 40 + slot * 8);
        }
    }

    // all threads: wait final commit on each of the 4 slots
    {
        uint32_t ph = ((uint32_t)(NQ >> 2) - 1) & 1;
#pragma unroll
        for (int s = 0; s < 4; s++) MBARRIER_WAIT_PARITY(sb + 40 + s * 8, ph);
    }
    TCGEN05_FENCE_AFTER();
    __syncthreads();

    // epilogue: warp w: m-block = w>>2, rows (w&3)*32+lid of that block; 256 cols each
    const int mb = wid >> 2;
    const int row = m0 + mb * 128 + (wid & 3) * 32 + lid;
    const uint32_t tcol0 = tmem + mb * 256;
#pragma unroll
    for (int cq = 0; cq < 8; cq++) {
        const int cb = cq * 32;
        uint32_t regs[32];
        TCGEN05_LD_32X32B_X32(regs, tcol0 + cb);
        TCGEN05_WAIT_LD();
        float v[32];
#pragma unroll
        for (int c = 0; c < 32; c++) {
            float bv = bias ? bias[n0 + cb + c] : 0.0f;
            v[c] = scale * (__uint_as_float(regs[c]) + bv);
        }
        if (C) {
            float* crow = C + (size_t)row * ldc + n0 + cb;
#pragma unroll
            for (int c4 = 0; c4 < 8; c4++) {
                *(float4*)(crow + c4 * 4) = make_float4(v[c4*4], v[c4*4+1], v[c4*4+2], v[c4*4+3]);
            }
        }
        if (Ch) {
            __nv_bfloat16 hv[32], lv[32];
#pragma unroll
            for (int c = 0; c < 32; c++) split2(v[c], hv[c], lv[c]);
            __nv_bfloat16* hrow = Ch + (size_t)row * ldc + n0 + cb;
            __nv_bfloat16* lrow = Cl + (size_t)row * ldc + n0 + cb;
#pragma unroll
            for (int c8 = 0; c8 < 4; c8++) {
                *(uint4*)(hrow + c8 * 8) = *(uint4*)&hv[c8 * 8];
                *(uint4*)(lrow + c8 * 8) = *(uint4*)&lv[c8 * 8];
            }
        }
    }
    TCGEN05_FENCE_BEFORE();
    __syncthreads();
    if (tid == 0) {
#pragma unroll
        for (int s = 0; s < 4; s++) { MBARRIER_INVAL(sb + 8 + s * 8); MBARRIER_INVAL(sb + 40 + s * 8); }
    }
    __syncthreads();
    if (wid == 0) { TCGEN05_DEALLOC(tmem, 512); }

#else  // ---------------- FMA fallback (256 threads; correctness-only path) ----------------
    (void)smem;
    const int tx = tid & 15, ty = tid >> 4;   // 16 x 16

    for (int sub = 0; sub < 4; sub++) {
        const int mbase = m0 + (sub >> 1) * 128;
        const int nbase = n0 + (sub & 1) * 128;
        float acc[8][8];
#pragma unroll
        for (int i = 0; i < 8; i++)
#pragma unroll
            for (int j = 0; j < 8; j++) acc[i][j] = 0.0f;

        for (int k0 = 0; k0 < K; k0 += 16) {
#pragma unroll
            for (int kk = 0; kk < 16; kk++) {
                float a[8], b[8];
#pragma unroll
                for (int u = 0; u < 8; u++) {
                    size_t ia = (size_t)(mbase + ty * 8 + u) * lda + k0 + kk;
                    a[u] = __bfloat162float(Ah[ia]) + __bfloat162float(Al[ia]);
                }
#pragma unroll
                for (int u = 0; u < 8; u++) {
                    size_t ib = (size_t)(nbase + tx * 8 + u) * ldb + k0 + kk;
                    b[u] = __bfloat162float(Bh[ib]) + __bfloat162float(Bl[ib]);
                }
#pragma unroll
                for (int i = 0; i < 8; i++)
#pragma unroll
                    for (int j = 0; j < 8; j++)
                        acc[i][j] = fmaf(a[i], b[j], acc[i][j]);
            }
        }

        float bv[8];
#pragma unroll
        for (int j = 0; j < 8; j++) bv[j] = bias ? bias[nbase + tx * 8 + j] : 0.0f;
#pragma unroll
        for (int i = 0; i < 8; i++) {
            int r = mbase + ty * 8 + i;
            float v[8];
#pragma unroll
            for (int j = 0; j < 8; j++) v[j] = scale * (acc[i][j] + bv[j]);
            if (C) {
                float* crow = C + (size_t)r * ldc + nbase + tx * 8;
                *(float4*)(crow + 0) = make_float4(v[0], v[1], v[2], v[3]);
                *(float4*)(crow + 4) = make_float4(v[4], v[5], v[6], v[7]);
            }
            if (Ch) {
                __nv_bfloat16 hv[8], lv[8];
#pragma unroll
                for (int j = 0; j < 8; j++) split2(v[j], hv[j], lv[j]);
                *(uint4*)(Ch + (size_t)r * ldc + nbase + tx * 8) = *(uint4*)hv;
                *(uint4*)(Cl + (size_t)r * ldc + nbase + tx * 8) = *(uint4*)lv;
            }
        }
    }
#endif
}

// ================= attention kernels =================
__device__ __forceinline__ float4 load_v4(const __nv_bfloat16* vh, const __nv_bfloat16* vl,
                                          size_t idx)
{
    __nv_bfloat162 h0 = *(const __nv_bfloat162*)(vh + idx);
    __nv_bfloat162 h1 = *(const __nv_bfloat162*)(vh + idx + 2);
    __nv_bfloat162 l0 = *(const __nv_bfloat162*)(vl + idx);
    __nv_bfloat162 l1 = *(const __nv_bfloat162*)(vl + idx + 2);
    float2 fh0 = __bfloat1622float2(h0), fh1 = __bfloat1622float2(h1);
    float2 fl0 = __bfloat1622float2(l0), fl1 = __bfloat1622float2(l1);
    return make_float4(fh0.x + fl0.x, fh0.y + fl0.y, fh1.x + fl1.x, fh1.y + fl1.y);
}

__global__ __launch_bounds__(256)
void chunk_kv_kernel()
{
    __shared__ float Ks[16][TP];
    __shared__ float Vs[16][TP];
    const int c = blockIdx.x, h = blockIdx.y, b = blockIdx.z;
    const int tid = threadIdx.x;
    const int tx = tid & 15, ty = tid >> 4;
    const float s = head_slope(h);

    const float* kbase = g_ke + ((size_t)(b * SEQ + c * CHUNKL)) * DMODEL + h * DHEAD;
    const __nv_bfloat16* vh = g_qkv_h + ((size_t)(b * SEQ + c * CHUNKL)) * NQKV + 4096 + h * DHEAD;
    const __nv_bfloat16* vl = g_qkv_l + ((size_t)(b * SEQ + c * CHUNKL)) * NQKV + 4096 + h * DHEAD;

    float acc[8][8];
#pragma unroll
    for (int i = 0; i < 8; i++)
#pragma unroll
        for (int j = 0; j < 8; j++) acc[i][j] = 0.0f;

    for (int j0 = 0; j0 < CHUNKL; j0 += 16) {
#pragma unroll
        for (int it = 0; it < 2; it++) {
            int f   = tid + it * 256;
            int row = f >> 5;
            int c4  = (f & 31) * 4;
            int j   = j0 + row;
            float kd = expf(-s * (float)(CHUNKL - 1 - j));
            float4 kv = *(const float4*)(kbase + (size_t)j * DMODEL + c4);
            kv.x *= kd; kv.y *= kd; kv.z *= kd; kv.w *= kd;
            *(float4*)&Ks[row][c4] = kv;
            *(float4*)&Vs[row][c4] = load_v4(vh, vl, (size_t)j * NQKV + c4);
        }
        __syncthreads();
#pragma unroll
        for (int kk = 0; kk < 16; kk++) {
            float a[8], bb[8];
#pragma unroll
            for (int u = 0; u < 8; u++) a[u]  = Ks[kk][ty * 8 + u];
#pragma unroll
            for (int u = 0; u < 8; u++) bb[u] = Vs[kk][tx * 8 + u];
#pragma unroll
            for (int i = 0; i < 8; i++)
#pragma unroll
                for (int j = 0; j < 8; j++)
                    acc[i][j] = fmaf(a[i], bb[j], acc[i][j]);
        }
        __syncthreads();
    }

    float* gout = g_st + ((size_t)((b * NHEAD + h) * NCHUNK + c)) * (128 * 128);
#pragma unroll
    for (int i = 0; i < 8; i++) {
        float* row = gout + (size_t)(ty * 8 + i) * 128 + tx * 8;
        *(float4*)(row + 0) = make_float4(acc[i][0], acc[i][1], acc[i][2], acc[i][3]);
        *(float4*)(row + 4) = make_float4(acc[i][4], acc[i][5], acc[i][6], acc[i][7]);
    }
}

__global__ __launch_bounds__(256)
void scan_kernel()
{
    const int bh = blockIdx.y;
    const int h  = bh & (NHEAD - 1);
    const float s   = head_slope(h);
    const float lam = expf(-s * (float)CHUNKL);
    const int e = blockIdx.x * 256 + threadIdx.x;
    float* base = g_st + (size_t)bh * NCHUNK * (128 * 128) + e;
    float S = 0.0f;
#pragma unroll 4
    for (int c = 0; c < NCHUNK; c++) {
        float g = base[(size_t)c * (128 * 128)];
        base[(size_t)c * (128 * 128)] = S;
        S = fmaf(lam, S, g);
    }
}

__global__ __launch_bounds__(256)
void chunk_out_kernel()
{
    extern __shared__ float sm[];
    float* Ash = sm;
    float* T1  = sm + 128 * APITCH;
    float* T2  = T1 + 16 * TP;

    const int c = blockIdx.x, hh = blockIdx.y, b = blockIdx.z;
    const int tid = threadIdx.x;
    const int tx = tid & 15, ty = tid >> 4;
    const float s = head_slope(hh);

    const size_t tok0 = (size_t)(b * SEQ + c * CHUNKL);
    const float* qbase = g_qe + tok0 * DMODEL + hh * DHEAD;
    const float* kbase = g_ke + tok0 * DMODEL + hh * DHEAD;
    const __nv_bfloat16* vh = g_qkv_h + tok0 * NQKV + 4096 + hh * DHEAD;
    const __nv_bfloat16* vl = g_qkv_l + tok0 * NQKV + 4096 + hh * DHEAD;
    const float* Sbase = g_st + ((size_t)((b * NHEAD + hh) * NCHUNK + c)) * (128 * 128);

    float acc[8][8];
#pragma unroll
    for (int i = 0; i < 8; i++)
#pragma unroll
        for (int j = 0; j < 8; j++) acc[i][j] = 0.0f;

    for (int d0 = 0; d0 < DHEAD; d0 += 16) {
#pragma unroll
        for (int it = 0; it < 2; it++) {
            int f   = tid + it * 256;
            int row = f >> 2;
            int kq  = (f & 3) * 4;
            float4 qv = *(const float4*)(qbase + (size_t)row * DMODEL + d0 + kq);
            T1[(kq + 0) * TP + row] = qv.x; T1[(kq + 1) * TP + row] = qv.y;
            T1[(kq + 2) * TP + row] = qv.z; T1[(kq + 3) * TP + row] = qv.w;
            float4 kv = *(const float4*)(kbase + (size_t)row * DMODEL + d0 + kq);
            T2[(kq + 0) * TP + row] = kv.x; T2[(kq + 1) * TP + row] = kv.y;
            T2[(kq + 2) * TP + row] = kv.z; T2[(kq + 3) * TP + row] = kv.w;
        }
        __syncthreads();
#pragma unroll
        for (int kk = 0; kk < 16; kk++) {
            float a[8], bb[8];
#pragma unroll
            for (int u = 0; u < 8; u++) a[u]  = T1[kk * TP + ty * 8 + u];
#pragma unroll
            for (int u = 0; u < 8; u++) bb[u] = T2[kk * TP + tx * 8 + u];
#pragma unroll
            for (int i = 0; i < 8; i++)
#pragma unroll
                for (int j = 0; j < 8; j++)
                    acc[i][j] = fmaf(a[i], bb[j], acc[i][j]);
        }
        __syncthreads();
    }

#pragma unroll
    for (int jj = 0; jj < 8; jj++) {
#pragma unroll
        for (int ii = 0; ii < 8; ii++) {
            int i = ty * 8 + ii, j = tx * 8 + jj;
            float v = (i >= j) ? acc[ii][jj] * expf(-s * (float)(i - j)) : 0.0f;
            Ash[j * APITCH + i] = v;
        }
    }
    __syncthreads();

    float accO[8][8];
#pragma unroll
    for (int i = 0; i < 8; i++)
#pragma unroll
        for (int j = 0; j < 8; j++) accO[i][j] = 0.0f;

    for (int j0 = 0; j0 < CHUNKL; j0 += 16) {
#pragma unroll
        for (int it = 0; it < 2; it++) {
            int f   = tid + it * 256;
            int row = f >> 5;
            int c4  = (f & 31) * 4;
            *(float4*)&T1[row * TP + c4] = load_v4(vh, vl, (size_t)(j0 + row) * NQKV + c4);
        }
        __syncthreads();
#pragma unroll
        for (int kk = 0; kk < 16; kk++) {
            float a[8], bb[8];
#pragma unroll
            for (int u = 0; u < 8; u++) a[u]  = Ash[(j0 + kk) * APITCH + ty * 8 + u];
#pragma unroll
            for (int u = 0; u < 8; u++) bb[u] = T1[kk * TP + tx * 8 + u];
#pragma unroll
            for (int i = 0; i < 8; i++)
#pragma unroll
                for (int j = 0; j < 8; j++)
                    accO[i][j] = fmaf(a[i], bb[j], accO[i][j]);
        }
        __syncthreads();
    }

    float acc2[8][8];
#pragma unroll
    for (int i = 0; i < 8; i++)
#pragma unroll
        for (int j = 0; j < 8; j++) acc2[i][j] = 0.0f;

    for (int d0 = 0; d0 < DHEAD; d0 += 16) {
#pragma unroll
        for (int it = 0; it < 2; it++) {
            int f   = tid + it * 256;
            int row = f >> 2;
            int kq  = (f & 3) * 4;
            float4 qv = *(const float4*)(qbase + (size_t)row * DMODEL + d0 + kq);
            T1[(kq + 0) * TP + row] = qv.x; T1[(kq + 1) * TP + row] = qv.y;
            T1[(kq + 2) * TP + row] = qv.z; T1[(kq + 3) * TP + row] = qv.w;
        }
#pragma unroll
        for (int it = 0; it < 2; it++) {
            int f   = tid + it * 256;
            int row = f >> 5;
            int c4  = (f & 31) * 4;
            float4 sv = *(const float4*)(Sbase + (size_t)(d0 + row) * 128 + c4);
            *(float4*)&T2[row * TP + c4] = sv;
        }
        __syncthreads();
#pragma unroll
        for (int kk = 0; kk < 16; kk++) {
            float a[8], bb[8];
#pragma unroll
            for (int u = 0; u < 8; u++) a[u]  = T1[kk * TP + ty * 8 + u];
#pragma unroll
            for (int u = 0; u < 8; u++) bb[u] = T2[kk * TP + tx * 8 + u];
#pragma unroll
            for (int i = 0; i < 8; i++)
#pragma unroll
                for (int j = 0; j < 8; j++)
                    acc2[i][j] = fmaf(a[i], bb[j], acc2[i][j]);
        }
        __syncthreads();
    }

    float vals[8][8];
#pragma unroll
    for (int ii = 0; ii < 8; ii++) {
        float qd = expf(-s * (float)(ty * 8 + ii + 1));
#pragma unroll
        for (int jj = 0; jj < 8; jj++)
            vals[ii][jj] = accO[ii][jj] + qd * acc2[ii][jj];
    }

#pragma unroll
    for (int ii = 0; ii < 8; ii++) {
        float ps = 0.0f, pq = 0.0f;
#pragma unroll
        for (int jj = 0; jj < 8; jj++) { float v = vals[ii][jj]; ps += v; pq += v * v; }
        T1[(ty * 8 + ii) * 16 + tx] = ps;
        T2[(ty * 8 + ii) * 16 + tx] = pq;
    }
    __syncthreads();

    if (tid < 128) {
        float s1 = 0.0f, s2 = 0.0f;
#pragma unroll
        for (int t = 0; t < 16; t++) { s1 += T1[tid * 16 + t]; s2 += T2[tid * 16 + t]; }
        float mu  = s1 * (1.0f / 128.0f);
        float var = s2 * (1.0f / 128.0f) - mu * mu;
        Ash[tid]       = mu;
        Ash[128 + tid] = rsqrtf(var + 1e-5f);
    }
    __syncthreads();

    float* obase = g_y + tok0 * DMODEL + hh * DHEAD;
    __nv_bfloat16* ohbase = g_y_h + tok0 * DMODEL + hh * DHEAD;
    __nv_bfloat16* olbase = g_y_l + tok0 * DMODEL + hh * DHEAD;
#pragma unroll
    for (int ii = 0; ii < 8; ii++) {
        int i = ty * 8 + ii;
        float mu = Ash[i], rs = Ash[128 + i];
        float o[8];
#pragma unroll
        for (int jj = 0; jj < 8; jj++) o[jj] = (vals[ii][jj] - mu) * rs;
        float* row = obase + (size_t)i * DMODEL + tx * 8;
        *(float4*)(row + 0) = make_float4(o[0], o[1], o[2], o[3]);
        *(float4*)(row + 4) = make_float4(o[4], o[5], o[6], o[7]);
        __nv_bfloat16 hv[8], lv[8];
#pragma unroll
        for (int jj = 0; jj < 8; jj++) split2(o[jj], hv[jj], lv[jj]);
        *(uint4*)(ohbase + (size_t)i * DMODEL + tx * 8) = *(uint4*)hv;
        *(uint4*)(olbase + (size_t)i * DMODEL + tx * 8) = *(uint4*)lv;
    }
}

// ================= host launcher =================
extern "C" void kernel_launch(void* const* d_in, const int* in_sizes, int n_in,
                              void* d_out, int out_size)
{
    (void)in_sizes; (void)n_in; (void)out_size;
    const float* x       = (const float*)d_in[0];
    const float* W_in    = (const float*)d_in[1];
    const float* W_embed = (const float*)d_in[2];
    const float* b_embed = (const float*)d_in[3];
    const float* W_out   = (const float*)d_in[4];
    float* out = (float*)d_out;

    float *qe, *ke, *y;
    __nv_bfloat16 *qkv_h, *qkv_l, *x_h, *x_l, *win_h, *win_l, *wemb_h, *wemb_l, *wout_h, *wout_l, *y_h, *y_l;
    cudaGetSymbolAddress((void**)&qe,    g_qe);
    cudaGetSymbolAddress((void**)&ke,    g_ke);
    cudaGetSymbolAddress((void**)&y,     g_y);
    cudaGetSymbolAddress((void**)&qkv_h, g_qkv_h);
    cudaGetSymbolAddress((void**)&qkv_l, g_qkv_l);
    cudaGetSymbolAddress((void**)&x_h,   g_x_h);
    cudaGetSymbolAddress((void**)&x_l,   g_x_l);
    cudaGetSymbolAddress((void**)&win_h, g_win_h);
    cudaGetSymbolAddress((void**)&win_l, g_win_l);
    cudaGetSymbolAddress((void**)&wemb_h,g_wemb_h);
    cudaGetSymbolAddress((void**)&wemb_l,g_wemb_l);
    cudaGetSymbolAddress((void**)&wout_h,g_wout_h);
    cudaGetSymbolAddress((void**)&wout_l,g_wout_l);
    cudaGetSymbolAddress((void**)&y_h,   g_y_h);
    cudaGetSymbolAddress((void**)&y_l,   g_y_l);

    const int smem_k5 = (128 * APITCH + 2 * 16 * TP) * 4;
    cudaFuncSetAttribute(chunk_out_kernel, cudaFuncAttributeMaxDynamicSharedMemorySize, smem_k5);
    cudaFuncSetAttribute(gemm_tc_kernel, cudaFuncAttributeMaxDynamicSharedMemorySize, GEMM_SMEM);

    // splits
    {
        long long n4;
        n4 = (long long)NTOK * DMODEL / 4;
        split_kernel<<<(unsigned)((n4 + 255) / 256), 256>>>(x, x_h, x_l, n4);
        n4 = (long long)NQKV * DMODEL / 4;
        split_kernel<<<(unsigned)((n4 + 255) / 256), 256>>>(W_in, win_h, win_l, n4);
        n4 = (long long)DMODEL * DMODEL / 4;
        split_kernel<<<(unsigned)((n4 + 255) / 256), 256>>>(W_embed, wemb_h, wemb_l, n4);
        split_kernel<<<(unsigned)((n4 + 255) / 256), 256>>>(W_out, wout_h, wout_l, n4);
    }

    // 1) qkv = x @ W_in^T  (bf16 hi/lo only)
    gemm_tc_kernel<<<dim3(NQKV / 256, NTOK / 256), 256, GEMM_SMEM>>>(
        x_h, x_l, DMODEL, win_h, win_l, DMODEL,
        nullptr, qkv_h, qkv_l, NQKV, DMODEL, nullptr, 1.0f);

    // 2) qe = qkv[:,0:2048] @ W_embed^T + b
    gemm_tc_kernel<<<dim3(DMODEL / 256, NTOK / 256), 256, GEMM_SMEM>>>(
        qkv_h, qkv_l, NQKV, wemb_h, wemb_l, DMODEL,
        qe, nullptr, nullptr, DMODEL, DMODEL, b_embed, 1.0f);

    // 3) ke = (qkv[:,2048:4096] @ W_embed^T + b) * QK_SCALE
    gemm_tc_kernel<<<dim3(DMODEL / 256, NTOK / 256), 256, GEMM_SMEM>>>(
        qkv_h + 2048, qkv_l + 2048, NQKV, wemb_h, wemb_l, DMODEL,
        ke, nullptr, nullptr, DMODEL, DMODEL, b_embed, QK_SCALE);

    // 4) per-chunk KV products
    chunk_kv_kernel<<<dim3(NCHUNK, NHEAD, BATCH), 256>>>();

    // 5) state scan
    scan_kernel<<<dim3(128 * 128 / 256, BATCH * NHEAD), 256>>>();

    // 6) per-chunk output + fused LayerNorm (+ bf16 split of y)
    chunk_out_kernel<<<dim3(NCHUNK, NHEAD, BATCH), 256, smem_k5>>>();

    // 7) out = y @ W_out^T
    gemm_tc_kernel<<<dim3(DMODEL / 256, NTOK / 256), 256, GEMM_SMEM>>>(
        y_h, y_l, DMODEL, wout_h, wout_l, DMODEL,
        out, nullptr, nullptr, DMODEL, DMODEL, nullptr, 1.0f);
}